// round 4
// baseline (speedup 1.0000x reference)
#include <cuda_runtime.h>
#include <cuda_fp16.h>
#include <cstdint>

#define NN 100000
#define NE 800000
#define FH 64
#define FO 16
#define SCAN_T 1024

// ---------------- scratch ----------------------------------------------------
__device__ int     g_cnt[NN + 128];   // [0,NN): in-degree; [NN,..): lookback slots
__device__ int     g_off[NN];         // CSR offsets; AFTER scatter = end pointers
__device__ float   g_dinv[NN];
__device__ int2    g_sn[NE];          // CSR payload: (src, nrm bits)
__device__ __half2 g_tmp1h[(size_t)NN * 32];   // x @ W1, fp16 storage
__device__ float   g_h[(size_t)NN * FH];
__device__ float   g_tmp2[(size_t)NN * FO];

// ---------------- per-block dtype detect (blockDim.x >= 256) -----------------
__device__ __forceinline__ int block_detect64(const void* edge, int n_nodes) {
    const long long* p = (const long long*)edge;
    long long v = p[threadIdx.x & 255];
    bool bad = (v < 0 || v >= (long long)n_nodes);
    return __syncthreads_or(bad ? 1 : 0) ? 0 : 1;
}

// ---------------- histogram over destination column --------------------------
__global__ void k_hist(const void* edge, int E, int n_nodes) {
    int is64 = block_detect64(edge, n_nodes);
    int e = blockIdx.x * blockDim.x + threadIdx.x;
    if (e >= E) return;
    int c = is64 ? (int)((const long long*)edge)[e + E]
                 : ((const int*)edge)[e + E];
    atomicAdd(&g_cnt[c], 1);
}

// ---------------- fused scan (deadlock-free lookback) + dinv -----------------
__global__ void k_scan(int n) {
    __shared__ int s[SCAN_T];
    __shared__ int s_pref;
    int b = blockIdx.x, t = threadIdx.x;
    int i = b * SCAN_T + t;
    int val = 0;
    if (i < n) {
        val = g_cnt[i];
        g_dinv[i] = rsqrtf((float)val + 1.0f);   // +1 self loop
    }
    s[t] = val;
    __syncthreads();
    for (int d = 1; d < SCAN_T; d <<= 1) {
        int add = (t >= d) ? s[t - d] : 0;
        __syncthreads();
        s[t] += add;
        __syncthreads();
    }
    if (t == SCAN_T - 1) atomicExch(&g_cnt[NN + b], s[t] + 1);   // publish first
    if (t == 0) s_pref = 0;
    __syncthreads();
    if (t < b) {
        int v;
        do { v = atomicAdd(&g_cnt[NN + t], 0); } while (v == 0);
        atomicAdd(&s_pref, v - 1);
    }
    __syncthreads();
    if (i < n) g_off[i] = s[t] - val + s_pref;
}

// ---------------- counting-sort scatter (mutates g_off -> end pointers) ------
__global__ void k_scatter(const void* edge, int E, int n_nodes) {
    int is64 = block_detect64(edge, n_nodes);
    int e = blockIdx.x * blockDim.x + threadIdx.x;
    if (e >= E) return;
    int r, c;
    if (is64) {
        const long long* p = (const long long*)edge;
        r = (int)p[e]; c = (int)p[e + E];
    } else {
        const int* p = (const int*)edge;
        r = p[e]; c = p[e + E];
    }
    float nr = g_dinv[r] * g_dinv[c];
    int pos = atomicAdd(&g_off[c], 1);
    g_sn[pos] = make_int2(r, __float_as_int(nr));
}

// ---------------- packed f32x2 helpers ---------------------------------------
__device__ __forceinline__ unsigned long long dup2(float v) {
    unsigned long long r;
    unsigned int u = __float_as_uint(v);
    asm("mov.b64 %0, {%1, %1};" : "=l"(r) : "r"(u));
    return r;
}
__device__ __forceinline__ unsigned long long packf2(float lo, float hi) {
    unsigned long long r;
    asm("mov.b64 %0, {%1, %2};" : "=l"(r) : "r"(__float_as_uint(lo)), "r"(__float_as_uint(hi)));
    return r;
}
__device__ __forceinline__ void fma2(unsigned long long& d,
                                     unsigned long long a, unsigned long long b) {
    asm("fma.rn.f32x2 %0, %1, %2, %0;" : "+l"(d) : "l"(a), "l"(b));
}
__device__ __forceinline__ float2 unpk2(unsigned long long v) {
    unsigned int l, h;
    asm("mov.b64 {%0, %1}, %2;" : "=r"(l), "=r"(h) : "l"(v));
    return make_float2(__uint_as_float(l), __uint_as_float(h));
}

// ---------------- GEMM1: tmp1h[n,64](fp16) = A[n,64] @ W[64,64] --------------
// 128 threads; tile 128 rows x 64 cols; thread = 8 rows (interleaved) x 8 cols.
// f32x2 packed across adjacent columns; W read via __ldg (L1-resident, 16KB).
__global__ void k_gemm64(const float* __restrict__ A,
                         const float* __restrict__ W,
                         __half2* __restrict__ outh, int n) {
    __shared__ float As[128][66];           // pad 66: ty-stride 66 words -> no conflict

    int tid  = threadIdx.x;
    int base = blockIdx.x * 128;
    int tx = tid & 7;                        // col group: c0 = tx*8
    int ty = tid >> 3;                       // row lane 0..15; rows = ty + 16*i

    // stage A tile (streaming loads; don't pollute L1 where W lives)
    for (int idx = tid; idx < 128 * 16; idx += 128) {
        int r  = idx >> 4;
        int k4 = (idx & 15) << 2;
        float4 v = make_float4(0.f, 0.f, 0.f, 0.f);
        int gr = base + r;
        if (gr < n) v = __ldcs((const float4*)(A + (size_t)gr * 64 + k4));
        As[r][k4]     = v.x;
        As[r][k4 + 1] = v.y;
        As[r][k4 + 2] = v.z;
        As[r][k4 + 3] = v.w;
    }
    __syncthreads();

    const float4* W4 = (const float4*)W;    // W[k][c] row-major, 16 float4 per k
    unsigned long long acc[8][4];
#pragma unroll
    for (int i = 0; i < 8; i++)
#pragma unroll
        for (int j = 0; j < 4; j++) acc[i][j] = 0ull;

#pragma unroll 2
    for (int k = 0; k < 64; k++) {
        float4 wa = __ldg(&W4[k * 16 + tx * 2]);
        float4 wb = __ldg(&W4[k * 16 + tx * 2 + 1]);
        unsigned long long w0 = packf2(wa.x, wa.y);
        unsigned long long w1 = packf2(wa.z, wa.w);
        unsigned long long w2 = packf2(wb.x, wb.y);
        unsigned long long w3 = packf2(wb.z, wb.w);
#pragma unroll
        for (int i = 0; i < 8; i++) {
            unsigned long long a = dup2(As[ty + 16 * i][k]);
            fma2(acc[i][0], a, w0);
            fma2(acc[i][1], a, w1);
            fma2(acc[i][2], a, w2);
            fma2(acc[i][3], a, w3);
        }
    }

#pragma unroll
    for (int i = 0; i < 8; i++) {
        int gr = base + ty + 16 * i;
        if (gr < n) {
            float2 p0 = unpk2(acc[i][0]);
            float2 p1 = unpk2(acc[i][1]);
            float2 p2 = unpk2(acc[i][2]);
            float2 p3 = unpk2(acc[i][3]);
            __half2 h0 = __float22half2_rn(p0);
            __half2 h1 = __float22half2_rn(p1);
            __half2 h2 = __float22half2_rn(p2);
            __half2 h3 = __float22half2_rn(p3);
            uint4 v;
            v.x = *(unsigned int*)&h0;
            v.y = *(unsigned int*)&h1;
            v.z = *(unsigned int*)&h2;
            v.w = *(unsigned int*)&h3;
            *(uint4*)&outh[(size_t)gr * 32 + tx * 4] = v;
        }
    }
}

// ---------------- GEMM2: out[n,16] = A[n,64] @ W[64,16], scalar 4x4 ----------
__global__ void k_gemm16(const float* __restrict__ A,
                         const float* __restrict__ W,
                         float* __restrict__ out, int n) {
    __shared__ float XsT[64][68];
    __shared__ float Ws[64 * 16];
    int tid  = threadIdx.x;                 // 64 threads
    int base = blockIdx.x * 64;

    for (int i = tid; i < 64 * 4; i += 64)
        ((float4*)Ws)[i] = ((const float4*)W)[i];
    for (int i = tid; i < 64 * 16; i += 64) {
        int r  = i >> 4;
        int k4 = (i & 15) << 2;
        float4 v = make_float4(0.f, 0.f, 0.f, 0.f);
        int gr = base + r;
        if (gr < n) v = *(const float4*)(A + (size_t)gr * 64 + k4);
        XsT[k4    ][r] = v.x;
        XsT[k4 + 1][r] = v.y;
        XsT[k4 + 2][r] = v.z;
        XsT[k4 + 3][r] = v.w;
    }
    __syncthreads();

    int tx = tid & 3, ty = tid >> 2;
    int c0 = tx * 4,  r0 = ty * 4;

    float acc[4][4];
#pragma unroll
    for (int i = 0; i < 4; i++)
#pragma unroll
        for (int j = 0; j < 4; j++) acc[i][j] = 0.f;

#pragma unroll 4
    for (int k = 0; k < 64; k++) {
        float4 a = *(const float4*)&XsT[k][r0];
        float4 w = *(const float4*)&Ws[k * 16 + c0];
        acc[0][0] += a.x * w.x; acc[0][1] += a.x * w.y; acc[0][2] += a.x * w.z; acc[0][3] += a.x * w.w;
        acc[1][0] += a.y * w.x; acc[1][1] += a.y * w.y; acc[1][2] += a.y * w.z; acc[1][3] += a.y * w.w;
        acc[2][0] += a.z * w.x; acc[2][1] += a.z * w.y; acc[2][2] += a.z * w.z; acc[2][3] += a.z * w.w;
        acc[3][0] += a.w * w.x; acc[3][1] += a.w * w.y; acc[3][2] += a.w * w.z; acc[3][3] += a.w * w.w;
    }
#pragma unroll
    for (int i = 0; i < 4; i++) {
        int gr = base + r0 + i;
        if (gr < n)
            *(float4*)(out + (size_t)gr * 16 + c0) =
                make_float4(acc[i][0], acc[i][1], acc[i][2], acc[i][3]);
    }
}

// ---------------- aggregation, layer 1 (F=64, fp16 source): warp/node --------
__global__ void k_agg1(const __half2* __restrict__ tmp,
                       const float2* __restrict__ b1,
                       float2* __restrict__ h, int n) {
    int i = (blockIdx.x * blockDim.x + threadIdx.x) >> 5;
    int lane = threadIdx.x & 31;
    if (i >= n) return;
    float di = g_dinv[i];
    float ws = di * di;
    float2 v = __half22float2(tmp[(size_t)i * 32 + lane]);
    float a0 = v.x * ws, a1 = v.y * ws;

    int e1 = g_off[i];
    int e  = e1 - g_cnt[i];
    for (; e + 4 <= e1; e += 4) {
        int2 q0 = g_sn[e];
        int2 q1 = g_sn[e + 1];
        int2 q2 = g_sn[e + 2];
        int2 q3 = g_sn[e + 3];
        float2 t0 = __half22float2(tmp[(size_t)q0.x * 32 + lane]);
        float2 t1 = __half22float2(tmp[(size_t)q1.x * 32 + lane]);
        float2 t2 = __half22float2(tmp[(size_t)q2.x * 32 + lane]);
        float2 t3 = __half22float2(tmp[(size_t)q3.x * 32 + lane]);
        float w0 = __int_as_float(q0.y), w1 = __int_as_float(q1.y);
        float w2 = __int_as_float(q2.y), w3 = __int_as_float(q3.y);
        a0 += t0.x * w0; a1 += t0.y * w0;
        a0 += t1.x * w1; a1 += t1.y * w1;
        a0 += t2.x * w2; a1 += t2.y * w2;
        a0 += t3.x * w3; a1 += t3.y * w3;
    }
    for (; e < e1; e++) {
        int2 q = g_sn[e];
        float2 t = __half22float2(tmp[(size_t)q.x * 32 + lane]);
        float w = __int_as_float(q.y);
        a0 += t.x * w; a1 += t.y * w;
    }
    float2 bb = b1[lane];
    h[(size_t)i * 32 + lane] = make_float2(fmaxf(a0 + bb.x, 0.f),
                                           fmaxf(a1 + bb.y, 0.f));
}

// ---------------- aggregation, layer 2 (F=16): 16 threads per node -----------
__global__ void k_agg2(const float* __restrict__ tmp,
                       const float* __restrict__ b2,
                       float* __restrict__ out, int n) {
    int i = (blockIdx.x * blockDim.x + threadIdx.x) >> 4;
    int l = threadIdx.x & 15;
    if (i >= n) return;
    float di = g_dinv[i];
    float a = tmp[(size_t)i * 16 + l] * di * di;

    int e1 = g_off[i];
    int e  = e1 - g_cnt[i];
    for (; e + 4 <= e1; e += 4) {
        int2 q0 = g_sn[e];
        int2 q1 = g_sn[e + 1];
        int2 q2 = g_sn[e + 2];
        int2 q3 = g_sn[e + 3];
        float t0 = tmp[(size_t)q0.x * 16 + l];
        float t1 = tmp[(size_t)q1.x * 16 + l];
        float t2 = tmp[(size_t)q2.x * 16 + l];
        float t3 = tmp[(size_t)q3.x * 16 + l];
        a += t0 * __int_as_float(q0.y);
        a += t1 * __int_as_float(q1.y);
        a += t2 * __int_as_float(q2.y);
        a += t3 * __int_as_float(q3.y);
    }
    for (; e < e1; e++) {
        int2 q = g_sn[e];
        a += tmp[(size_t)q.x * 16 + l] * __int_as_float(q.y);
    }
    out[(size_t)i * 16 + l] = a + b2[l];
}

// ---------------- launcher ---------------------------------------------------
extern "C" void kernel_launch(void* const* d_in, const int* in_sizes, int n_in,
                              void* d_out, int out_size) {
    const float* x  = (const float*)d_in[0];
    const void*  ei = d_in[1];
    const float* W1 = (const float*)d_in[2];
    const float* b1 = (const float*)d_in[3];
    const float* W2 = (const float*)d_in[4];
    const float* b2 = (const float*)d_in[5];
    float* out = (float*)d_out;

    const int n = in_sizes[0] / FH;
    const int E = in_sizes[1] / 2;

    __half2* tmp1h; cudaGetSymbolAddress((void**)&tmp1h, g_tmp1h);
    float*   h;     cudaGetSymbolAddress((void**)&h,     g_h);
    float*   tmp2;  cudaGetSymbolAddress((void**)&tmp2,  g_tmp2);
    int*     cnt;   cudaGetSymbolAddress((void**)&cnt,   g_cnt);

    const int T  = 256;
    const int gE = (E + T - 1) / T;
    const int nb = (n + SCAN_T - 1) / SCAN_T;

    cudaMemsetAsync(cnt, 0, (size_t)(NN + 128) * sizeof(int));
    k_hist   <<<gE, T>>>(ei, E, n);
    k_scan   <<<nb, SCAN_T>>>(n);
    k_scatter<<<gE, T>>>(ei, E, n);

    // Layer 1
    k_gemm64<<<(n + 127) / 128, 128>>>(x, W1, tmp1h, n);
    k_agg1  <<<(n * 32 + T - 1) / T, T>>>(tmp1h, (const float2*)b1, (float2*)h, n);

    // Layer 2
    k_gemm16<<<(n + 63) / 64, 64>>>(h, W2, tmp2, n);
    k_agg2  <<<(n * 16 + T - 1) / T, T>>>(tmp2, b2, out, n);

    (void)n_in; (void)out_size;
}

// round 7
// speedup vs baseline: 1.1623x; 1.1623x over previous
#include <cuda_runtime.h>
#include <cuda_fp16.h>
#include <cstdint>

#define NN 100000
#define NE 800000
#define FH 64
#define FO 16
#define SCAN_T 1024

// ---------------- scratch ----------------------------------------------------
__device__ int     g_cnt[NN + 128];   // [0,NN): in-degree; [NN,..): lookback slots
__device__ int     g_off[NN];         // CSR offsets; AFTER scatter = end pointers
__device__ float   g_dinv[NN];
__device__ int2    g_sn[NE];          // CSR payload: (src, nrm bits)
__device__ __half2 g_tmp1h[(size_t)NN * 32];   // x @ W1, fp16 storage
__device__ float   g_h[(size_t)NN * FH];
__device__ float   g_tmp2[(size_t)NN * FO];

// ---------------- per-block dtype detect (blockDim.x >= 256) -----------------
__device__ __forceinline__ int block_detect64(const void* edge, int n_nodes) {
    const long long* p = (const long long*)edge;
    long long v = p[threadIdx.x & 255];
    bool bad = (v < 0 || v >= (long long)n_nodes);
    return __syncthreads_or(bad ? 1 : 0) ? 0 : 1;
}

// ---------------- histogram over destination column --------------------------
__global__ void k_hist(const void* edge, int E, int n_nodes) {
    int is64 = block_detect64(edge, n_nodes);
    int e = blockIdx.x * blockDim.x + threadIdx.x;
    if (e >= E) return;
    int c = is64 ? (int)((const long long*)edge)[e + E]
                 : ((const int*)edge)[e + E];
    atomicAdd(&g_cnt[c], 1);
}

// ---------------- fused scan (deadlock-free lookback) + dinv -----------------
__global__ void k_scan(int n) {
    __shared__ int s[SCAN_T];
    __shared__ int s_pref;
    int b = blockIdx.x, t = threadIdx.x;
    int i = b * SCAN_T + t;
    int val = 0;
    if (i < n) {
        val = g_cnt[i];
        g_dinv[i] = rsqrtf((float)val + 1.0f);   // +1 self loop
    }
    s[t] = val;
    __syncthreads();
    for (int d = 1; d < SCAN_T; d <<= 1) {
        int add = (t >= d) ? s[t - d] : 0;
        __syncthreads();
        s[t] += add;
        __syncthreads();
    }
    if (t == SCAN_T - 1) atomicExch(&g_cnt[NN + b], s[t] + 1);   // publish first
    if (t == 0) s_pref = 0;
    __syncthreads();
    if (t < b) {
        int v;
        do { v = atomicAdd(&g_cnt[NN + t], 0); } while (v == 0);
        atomicAdd(&s_pref, v - 1);
    }
    __syncthreads();
    if (i < n) g_off[i] = s[t] - val + s_pref;
}

// ---------------- counting-sort scatter (mutates g_off -> end pointers) ------
__global__ void k_scatter(const void* edge, int E, int n_nodes) {
    int is64 = block_detect64(edge, n_nodes);
    int e = blockIdx.x * blockDim.x + threadIdx.x;
    if (e >= E) return;
    int r, c;
    if (is64) {
        const long long* p = (const long long*)edge;
        r = (int)p[e]; c = (int)p[e + E];
    } else {
        const int* p = (const int*)edge;
        r = p[e]; c = p[e + E];
    }
    float nr = g_dinv[r] * g_dinv[c];
    int pos = atomicAdd(&g_off[c], 1);
    g_sn[pos] = make_int2(r, __float_as_int(nr));
}

// ---------------- GEMM1 (tensor cores): tmp1h[n,64] = fp16(A[n,64] @ W[64,64])
// 256 threads = 8 warps; tile 128 rows. Warp w handles rows [w*16, w*16+16).
// mma.sync m16n8k16 f32.f16.f16.f32; A row-major in smem, W transposed [n][k].
// Pad stride 72 halfs -> all fragment LDS are bank-conflict-free (bank = g*4+t).
__global__ void k_gemm64_tc(const float* __restrict__ A,
                            const float* __restrict__ W,
                            __half2* __restrict__ outh, int n) {
    __shared__ __half Xs[128][72];     // x tile fp16 (later reused for C staging)
    __shared__ __half Wt[64][72];      // W1^T: [n][k]

    int tid  = threadIdx.x;
    int base = blockIdx.x * 128;
    int lane = tid & 31;
    int warp = tid >> 5;
    int g = lane >> 2, t = lane & 3;
    int row0 = warp * 16;

    // stage W transposed (coalesced gmem read, scattered one-time smem write)
    for (int idx = tid; idx < 64 * 64; idx += 256) {
        int k = idx >> 6, nn = idx & 63;
        Wt[nn][k] = __float2half_rn(W[idx]);
    }
    // stage X tile as fp16
    for (int idx = tid; idx < 128 * 16; idx += 256) {
        int r  = idx >> 4;
        int k4 = (idx & 15) << 2;
        float4 v = make_float4(0.f, 0.f, 0.f, 0.f);
        int gr = base + r;
        if (gr < n) v = *(const float4*)(A + (size_t)gr * 64 + k4);
        *(__half2*)&Xs[r][k4]     = __floats2half2_rn(v.x, v.y);
        *(__half2*)&Xs[r][k4 + 2] = __floats2half2_rn(v.z, v.w);
    }
    __syncthreads();

    float acc[8][4];
#pragma unroll
    for (int nt = 0; nt < 8; nt++)
#pragma unroll
        for (int j = 0; j < 4; j++) acc[nt][j] = 0.f;

#pragma unroll
    for (int k0 = 0; k0 < 64; k0 += 16) {
        unsigned ra0 = *(const unsigned*)&Xs[row0 + g    ][k0 + 2 * t];
        unsigned ra1 = *(const unsigned*)&Xs[row0 + g + 8][k0 + 2 * t];
        unsigned ra2 = *(const unsigned*)&Xs[row0 + g    ][k0 + 2 * t + 8];
        unsigned ra3 = *(const unsigned*)&Xs[row0 + g + 8][k0 + 2 * t + 8];
#pragma unroll
        for (int nt = 0; nt < 8; nt++) {
            unsigned rb0 = *(const unsigned*)&Wt[nt * 8 + g][k0 + 2 * t];
            unsigned rb1 = *(const unsigned*)&Wt[nt * 8 + g][k0 + 2 * t + 8];
            asm volatile(
                "mma.sync.aligned.m16n8k16.row.col.f32.f16.f16.f32 "
                "{%0,%1,%2,%3}, {%4,%5,%6,%7}, {%8,%9}, {%0,%1,%2,%3};"
                : "+f"(acc[nt][0]), "+f"(acc[nt][1]),
                  "+f"(acc[nt][2]), "+f"(acc[nt][3])
                : "r"(ra0), "r"(ra1), "r"(ra2), "r"(ra3),
                  "r"(rb0), "r"(rb1));
        }
    }

    // stage C into Xs (each warp writes only its own 16 rows)
    __syncwarp();
#pragma unroll
    for (int nt = 0; nt < 8; nt++) {
        int c0 = nt * 8 + 2 * t;
        *(__half2*)&Xs[row0 + g    ][c0] = __floats2half2_rn(acc[nt][0], acc[nt][1]);
        *(__half2*)&Xs[row0 + g + 8][c0] = __floats2half2_rn(acc[nt][2], acc[nt][3]);
    }
    __syncthreads();

    // coalesced copy to global (uint2 = 4 halfs; row byte-stride 144, 8B-aligned)
    for (int idx = tid; idx < 128 * 16; idx += 256) {
        int r = idx >> 4, c = idx & 15;
        int gr = base + r;
        if (gr < n) {
            uint2 v = *(const uint2*)&Xs[r][c * 4];
            *(uint2*)&outh[(size_t)gr * 32 + c * 2] = v;
        }
    }
}

// ---------------- GEMM2: out[n,16] = A[n,64] @ W[64,16], scalar 4x4 ----------
__global__ void k_gemm16(const float* __restrict__ A,
                         const float* __restrict__ W,
                         float* __restrict__ out, int n) {
    __shared__ float XsT[64][68];
    __shared__ float Ws[64 * 16];
    int tid  = threadIdx.x;                 // 64 threads
    int base = blockIdx.x * 64;

    for (int i = tid; i < 64 * 4; i += 64)
        ((float4*)Ws)[i] = ((const float4*)W)[i];
    for (int i = tid; i < 64 * 16; i += 64) {
        int r  = i >> 4;
        int k4 = (i & 15) << 2;
        float4 v = make_float4(0.f, 0.f, 0.f, 0.f);
        int gr = base + r;
        if (gr < n) v = *(const float4*)(A + (size_t)gr * 64 + k4);
        XsT[k4    ][r] = v.x;
        XsT[k4 + 1][r] = v.y;
        XsT[k4 + 2][r] = v.z;
        XsT[k4 + 3][r] = v.w;
    }
    __syncthreads();

    int tx = tid & 3, ty = tid >> 2;
    int c0 = tx * 4,  r0 = ty * 4;

    float acc[4][4];
#pragma unroll
    for (int i = 0; i < 4; i++)
#pragma unroll
        for (int j = 0; j < 4; j++) acc[i][j] = 0.f;

#pragma unroll 4
    for (int k = 0; k < 64; k++) {
        float4 a = *(const float4*)&XsT[k][r0];
        float4 w = *(const float4*)&Ws[k * 16 + c0];
        acc[0][0] += a.x * w.x; acc[0][1] += a.x * w.y; acc[0][2] += a.x * w.z; acc[0][3] += a.x * w.w;
        acc[1][0] += a.y * w.x; acc[1][1] += a.y * w.y; acc[1][2] += a.y * w.z; acc[1][3] += a.y * w.w;
        acc[2][0] += a.z * w.x; acc[2][1] += a.z * w.y; acc[2][2] += a.z * w.z; acc[2][3] += a.z * w.w;
        acc[3][0] += a.w * w.x; acc[3][1] += a.w * w.y; acc[3][2] += a.w * w.z; acc[3][3] += a.w * w.w;
    }
#pragma unroll
    for (int i = 0; i < 4; i++) {
        int gr = base + r0 + i;
        if (gr < n)
            *(float4*)(out + (size_t)gr * 16 + c0) =
                make_float4(acc[i][0], acc[i][1], acc[i][2], acc[i][3]);
    }
}

// ---------------- aggregation, layer 1 (F=64, fp16 source): warp/node --------
__global__ void k_agg1(const __half2* __restrict__ tmp,
                       const float2* __restrict__ b1,
                       float2* __restrict__ h, int n) {
    int i = (blockIdx.x * blockDim.x + threadIdx.x) >> 5;
    int lane = threadIdx.x & 31;
    if (i >= n) return;
    float di = g_dinv[i];
    float ws = di * di;
    float2 v = __half22float2(tmp[(size_t)i * 32 + lane]);
    float a0 = v.x * ws, a1 = v.y * ws;

    int e1 = g_off[i];
    int e  = e1 - g_cnt[i];
    for (; e + 4 <= e1; e += 4) {
        int2 q0 = g_sn[e];
        int2 q1 = g_sn[e + 1];
        int2 q2 = g_sn[e + 2];
        int2 q3 = g_sn[e + 3];
        float2 t0 = __half22float2(tmp[(size_t)q0.x * 32 + lane]);
        float2 t1 = __half22float2(tmp[(size_t)q1.x * 32 + lane]);
        float2 t2 = __half22float2(tmp[(size_t)q2.x * 32 + lane]);
        float2 t3 = __half22float2(tmp[(size_t)q3.x * 32 + lane]);
        float w0 = __int_as_float(q0.y), w1 = __int_as_float(q1.y);
        float w2 = __int_as_float(q2.y), w3 = __int_as_float(q3.y);
        a0 += t0.x * w0; a1 += t0.y * w0;
        a0 += t1.x * w1; a1 += t1.y * w1;
        a0 += t2.x * w2; a1 += t2.y * w2;
        a0 += t3.x * w3; a1 += t3.y * w3;
    }
    for (; e < e1; e++) {
        int2 q = g_sn[e];
        float2 t = __half22float2(tmp[(size_t)q.x * 32 + lane]);
        float w = __int_as_float(q.y);
        a0 += t.x * w; a1 += t.y * w;
    }
    float2 bb = b1[lane];
    h[(size_t)i * 32 + lane] = make_float2(fmaxf(a0 + bb.x, 0.f),
                                           fmaxf(a1 + bb.y, 0.f));
}

// ---------------- aggregation, layer 2 (F=16): 16 threads per node -----------
__global__ void k_agg2(const float* __restrict__ tmp,
                       const float* __restrict__ b2,
                       float* __restrict__ out, int n) {
    int i = (blockIdx.x * blockDim.x + threadIdx.x) >> 4;
    int l = threadIdx.x & 15;
    if (i >= n) return;
    float di = g_dinv[i];
    float a = tmp[(size_t)i * 16 + l] * di * di;

    int e1 = g_off[i];
    int e  = e1 - g_cnt[i];
    for (; e + 4 <= e1; e += 4) {
        int2 q0 = g_sn[e];
        int2 q1 = g_sn[e + 1];
        int2 q2 = g_sn[e + 2];
        int2 q3 = g_sn[e + 3];
        float t0 = tmp[(size_t)q0.x * 16 + l];
        float t1 = tmp[(size_t)q1.x * 16 + l];
        float t2 = tmp[(size_t)q2.x * 16 + l];
        float t3 = tmp[(size_t)q3.x * 16 + l];
        a += t0 * __int_as_float(q0.y);
        a += t1 * __int_as_float(q1.y);
        a += t2 * __int_as_float(q2.y);
        a += t3 * __int_as_float(q3.y);
    }
    for (; e < e1; e++) {
        int2 q = g_sn[e];
        a += tmp[(size_t)q.x * 16 + l] * __int_as_float(q.y);
    }
    out[(size_t)i * 16 + l] = a + b2[l];
}

// ---------------- launcher ---------------------------------------------------
extern "C" void kernel_launch(void* const* d_in, const int* in_sizes, int n_in,
                              void* d_out, int out_size) {
    const float* x  = (const float*)d_in[0];
    const void*  ei = d_in[1];
    const float* W1 = (const float*)d_in[2];
    const float* b1 = (const float*)d_in[3];
    const float* W2 = (const float*)d_in[4];
    const float* b2 = (const float*)d_in[5];
    float* out = (float*)d_out;

    const int n = in_sizes[0] / FH;
    const int E = in_sizes[1] / 2;

    __half2* tmp1h; cudaGetSymbolAddress((void**)&tmp1h, g_tmp1h);
    float*   h;     cudaGetSymbolAddress((void**)&h,     g_h);
    float*   tmp2;  cudaGetSymbolAddress((void**)&tmp2,  g_tmp2);
    int*     cnt;   cudaGetSymbolAddress((void**)&cnt,   g_cnt);

    const int T  = 256;
    const int gE = (E + T - 1) / T;
    const int nb = (n + SCAN_T - 1) / SCAN_T;

    cudaMemsetAsync(cnt, 0, (size_t)(NN + 128) * sizeof(int));
    k_hist   <<<gE, T>>>(ei, E, n);
    k_scan   <<<nb, SCAN_T>>>(n);
    k_scatter<<<gE, T>>>(ei, E, n);

    // Layer 1
    k_gemm64_tc<<<(n + 127) / 128, 256>>>(x, W1, tmp1h, n);
    k_agg1     <<<(n * 32 + T - 1) / T, T>>>(tmp1h, (const float2*)b1, (float2*)h, n);

    // Layer 2
    k_gemm16<<<(n + 63) / 64, 64>>>(h, W2, tmp2, n);
    k_agg2  <<<(n * 16 + T - 1) / T, T>>>(tmp2, b2, out, n);

    (void)n_in; (void)out_size;
}

// round 8
// speedup vs baseline: 1.4216x; 1.2231x over previous
#include <cuda_runtime.h>
#include <cuda_fp16.h>
#include <cstdint>

#define NN 100000
#define NE 800000
#define FH 64
#define FO 16
#define SCAN_T 1024

// ---------------- scratch ----------------------------------------------------
__device__ int     g_cnt[NN + 128];   // [0,NN): in-degree; [NN,..): lookback slots
__device__ int     g_off[NN];         // CSR offsets; AFTER scatter = end pointers
__device__ float   g_dinv[NN];
__device__ int2    g_sn[NE];          // CSR payload: (src, nrm bits)
__device__ __half2 g_tmp1h[(size_t)NN * 32];   // x @ W1, fp16
__device__ __half2 g_h[(size_t)NN * 32];       // relu(agg1)+b1, fp16
__device__ float   g_tmp2[(size_t)NN * FO];    // h @ W2, fp32
__device__ __half  g_w1t[64 * 64];    // W1^T fp16: [n][k]
__device__ __half  g_w2t[16 * 64];    // W2^T fp16: [n][k]

// ---------------- per-block dtype detect (blockDim.x >= 256) -----------------
__device__ __forceinline__ int block_detect64(const void* edge, int n_nodes) {
    const long long* p = (const long long*)edge;
    long long v = p[threadIdx.x & 255];
    bool bad = (v < 0 || v >= (long long)n_nodes);
    return __syncthreads_or(bad ? 1 : 0) ? 0 : 1;
}

// ---------------- histogram + (last block) weight prep -----------------------
__global__ void k_hist(const void* edge, int E, int n_nodes,
                       const float* __restrict__ W1,
                       const float* __restrict__ W2) {
    if (blockIdx.x == gridDim.x - 1) {        // weight-prep block (concurrent)
        int tid = threadIdx.x;
        for (int i = tid; i < 64 * 64; i += 256) {
            int k = i >> 6, nn = i & 63;      // W1[k][n] -> w1t[n][k]
            g_w1t[nn * 64 + k] = __float2half_rn(W1[i]);
        }
        for (int i = tid; i < 64 * 16; i += 256) {
            int k = i >> 4, nn = i & 15;      // W2[k][n] -> w2t[n][k]
            g_w2t[nn * 64 + k] = __float2half_rn(W2[i]);
        }
        return;
    }
    int is64 = block_detect64(edge, n_nodes);
    int e = blockIdx.x * blockDim.x + threadIdx.x;
    if (e >= E) return;
    int c = is64 ? (int)((const long long*)edge)[e + E]
                 : ((const int*)edge)[e + E];
    atomicAdd(&g_cnt[c], 1);
}

// ---------------- fused scan (deadlock-free lookback) + dinv -----------------
__global__ void k_scan(int n) {
    __shared__ int s[SCAN_T];
    __shared__ int s_pref;
    int b = blockIdx.x, t = threadIdx.x;
    int i = b * SCAN_T + t;
    int val = 0;
    if (i < n) {
        val = g_cnt[i];
        g_dinv[i] = rsqrtf((float)val + 1.0f);   // +1 self loop
    }
    s[t] = val;
    __syncthreads();
    for (int d = 1; d < SCAN_T; d <<= 1) {
        int add = (t >= d) ? s[t - d] : 0;
        __syncthreads();
        s[t] += add;
        __syncthreads();
    }
    if (t == SCAN_T - 1) atomicExch(&g_cnt[NN + b], s[t] + 1);   // publish first
    if (t == 0) s_pref = 0;
    __syncthreads();
    if (t < b) {
        int v;
        do { v = atomicAdd(&g_cnt[NN + t], 0); } while (v == 0);
        atomicAdd(&s_pref, v - 1);
    }
    __syncthreads();
    if (i < n) g_off[i] = s[t] - val + s_pref;
}

// ---------------- counting-sort scatter (mutates g_off -> end pointers) ------
__global__ void k_scatter(const void* edge, int E, int n_nodes) {
    int is64 = block_detect64(edge, n_nodes);
    int e = blockIdx.x * blockDim.x + threadIdx.x;
    if (e >= E) return;
    int r, c;
    if (is64) {
        const long long* p = (const long long*)edge;
        r = (int)p[e]; c = (int)p[e + E];
    } else {
        const int* p = (const int*)edge;
        r = p[e]; c = p[e + E];
    }
    float nr = g_dinv[r] * g_dinv[c];
    int pos = atomicAdd(&g_off[c], 1);
    g_sn[pos] = make_int2(r, __float_as_int(nr));
}

// ---------------- GEMM1 (TC): tmp1h[n,64](fp16) = A[n,64]f32 @ W1 ------------
// 256 thr / 8 warps; tile 128 rows; warp w -> rows [16w,16w+16); nt = 8 n-tiles.
__global__ void k_gemm64_tc(const float* __restrict__ A,
                            __half2* __restrict__ outh, int n) {
    __shared__ __half Xs[128][72];     // X tile fp16 (reused for C staging)
    __shared__ __half Wts[64][72];     // W1^T [n][k]

    int tid  = threadIdx.x;
    int base = blockIdx.x * 128;
    int lane = tid & 31;
    int warp = tid >> 5;
    int g = lane >> 2, t = lane & 3;
    int row0 = warp * 16;

    // stage Wt (pre-transposed fp16): 512 x uint4 coalesced
    for (int idx = tid; idx < 512; idx += 256) {
        uint4 v = *(const uint4*)&g_w1t[idx * 8];
        int row = idx >> 3, c8 = idx & 7;
        *(uint4*)&Wts[row][c8 * 8] = v;
    }
    // stage X tile as fp16
    for (int idx = tid; idx < 128 * 16; idx += 256) {
        int r  = idx >> 4;
        int k4 = (idx & 15) << 2;
        float4 v = make_float4(0.f, 0.f, 0.f, 0.f);
        int gr = base + r;
        if (gr < n) v = *(const float4*)(A + (size_t)gr * 64 + k4);
        *(__half2*)&Xs[r][k4]     = __floats2half2_rn(v.x, v.y);
        *(__half2*)&Xs[r][k4 + 2] = __floats2half2_rn(v.z, v.w);
    }
    __syncthreads();

    float acc[8][4];
#pragma unroll
    for (int nt = 0; nt < 8; nt++)
#pragma unroll
        for (int j = 0; j < 4; j++) acc[nt][j] = 0.f;

#pragma unroll
    for (int k0 = 0; k0 < 64; k0 += 16) {
        unsigned ra0 = *(const unsigned*)&Xs[row0 + g    ][k0 + 2 * t];
        unsigned ra1 = *(const unsigned*)&Xs[row0 + g + 8][k0 + 2 * t];
        unsigned ra2 = *(const unsigned*)&Xs[row0 + g    ][k0 + 2 * t + 8];
        unsigned ra3 = *(const unsigned*)&Xs[row0 + g + 8][k0 + 2 * t + 8];
#pragma unroll
        for (int nt = 0; nt < 8; nt++) {
            unsigned rb0 = *(const unsigned*)&Wts[nt * 8 + g][k0 + 2 * t];
            unsigned rb1 = *(const unsigned*)&Wts[nt * 8 + g][k0 + 2 * t + 8];
            asm volatile(
                "mma.sync.aligned.m16n8k16.row.col.f32.f16.f16.f32 "
                "{%0,%1,%2,%3}, {%4,%5,%6,%7}, {%8,%9}, {%0,%1,%2,%3};"
                : "+f"(acc[nt][0]), "+f"(acc[nt][1]),
                  "+f"(acc[nt][2]), "+f"(acc[nt][3])
                : "r"(ra0), "r"(ra1), "r"(ra2), "r"(ra3),
                  "r"(rb0), "r"(rb1));
        }
    }

    // stage C fp16 into Xs (each warp touches only its own 16 rows)
    __syncwarp();
#pragma unroll
    for (int nt = 0; nt < 8; nt++) {
        int c0 = nt * 8 + 2 * t;
        *(__half2*)&Xs[row0 + g    ][c0] = __floats2half2_rn(acc[nt][0], acc[nt][1]);
        *(__half2*)&Xs[row0 + g + 8][c0] = __floats2half2_rn(acc[nt][2], acc[nt][3]);
    }
    __syncthreads();

    // coalesced copy out (uint2 = 4 halfs; row stride 144B, 8B aligned)
    for (int idx = tid; idx < 128 * 16; idx += 256) {
        int r = idx >> 4, c = idx & 15;
        int gr = base + r;
        if (gr < n) {
            uint2 v = *(const uint2*)&Xs[r][c * 4];
            *(uint2*)&outh[(size_t)gr * 32 + c * 2] = v;
        }
    }
}

// ---------------- GEMM2 (TC): tmp2[n,16]f32 = h[n,64]fp16 @ W2 ---------------
// 256 thr / 8 warps; tile 128 rows; nt = 2 n-tiles; direct float2 stores.
__global__ void k_gemm16_tc(const __half2* __restrict__ Ah,
                            float* __restrict__ out, int n) {
    __shared__ __half Xs[128][72];
    __shared__ __half Wts[16][72];

    int tid  = threadIdx.x;
    int base = blockIdx.x * 128;
    int lane = tid & 31;
    int warp = tid >> 5;
    int g = lane >> 2, t = lane & 3;
    int row0 = warp * 16;

    // stage Wt2: 128 x uint4
    if (tid < 128) {
        uint4 v = *(const uint4*)&g_w2t[tid * 8];
        int row = tid >> 3, c8 = tid & 7;
        *(uint4*)&Wts[row][c8 * 8] = v;
    }
    // stage h tile (already fp16): 1024 x uint4, 4 iters
    for (int idx = tid; idx < 1024; idx += 256) {
        int r = idx >> 3, c8 = idx & 7;
        uint4 v = make_uint4(0u, 0u, 0u, 0u);
        int gr = base + r;
        if (gr < n) v = *(const uint4*)&Ah[(size_t)gr * 32 + c8 * 4];
        *(uint4*)&Xs[r][c8 * 8] = v;
    }
    __syncthreads();

    float acc[2][4];
#pragma unroll
    for (int nt = 0; nt < 2; nt++)
#pragma unroll
        for (int j = 0; j < 4; j++) acc[nt][j] = 0.f;

#pragma unroll
    for (int k0 = 0; k0 < 64; k0 += 16) {
        unsigned ra0 = *(const unsigned*)&Xs[row0 + g    ][k0 + 2 * t];
        unsigned ra1 = *(const unsigned*)&Xs[row0 + g + 8][k0 + 2 * t];
        unsigned ra2 = *(const unsigned*)&Xs[row0 + g    ][k0 + 2 * t + 8];
        unsigned ra3 = *(const unsigned*)&Xs[row0 + g + 8][k0 + 2 * t + 8];
#pragma unroll
        for (int nt = 0; nt < 2; nt++) {
            unsigned rb0 = *(const unsigned*)&Wts[nt * 8 + g][k0 + 2 * t];
            unsigned rb1 = *(const unsigned*)&Wts[nt * 8 + g][k0 + 2 * t + 8];
            asm volatile(
                "mma.sync.aligned.m16n8k16.row.col.f32.f16.f16.f32 "
                "{%0,%1,%2,%3}, {%4,%5,%6,%7}, {%8,%9}, {%0,%1,%2,%3};"
                : "+f"(acc[nt][0]), "+f"(acc[nt][1]),
                  "+f"(acc[nt][2]), "+f"(acc[nt][3])
                : "r"(ra0), "r"(ra1), "r"(ra2), "r"(ra3),
                  "r"(rb0), "r"(rb1));
        }
    }

    // direct fp32 stores: thread owns cols {nt*8+2t, +1} of rows row0+g, row0+g+8
#pragma unroll
    for (int nt = 0; nt < 2; nt++) {
        int c0 = nt * 8 + 2 * t;
        int gr0 = base + row0 + g;
        int gr1 = gr0 + 8;
        if (gr0 < n)
            *(float2*)&out[(size_t)gr0 * 16 + c0] = make_float2(acc[nt][0], acc[nt][1]);
        if (gr1 < n)
            *(float2*)&out[(size_t)gr1 * 16 + c0] = make_float2(acc[nt][2], acc[nt][3]);
    }
}

// ---------------- aggregation, layer 1 (F=64, fp16 in/out): warp/node --------
__global__ void k_agg1(const __half2* __restrict__ tmp,
                       const float2* __restrict__ b1,
                       __half2* __restrict__ h, int n) {
    int i = (blockIdx.x * blockDim.x + threadIdx.x) >> 5;
    int lane = threadIdx.x & 31;
    if (i >= n) return;
    float di = g_dinv[i];
    float ws = di * di;
    float2 v = __half22float2(tmp[(size_t)i * 32 + lane]);
    float a0 = v.x * ws, a1 = v.y * ws;

    int e1 = g_off[i];
    int e  = e1 - g_cnt[i];
    for (; e + 4 <= e1; e += 4) {
        int2 q0 = g_sn[e];
        int2 q1 = g_sn[e + 1];
        int2 q2 = g_sn[e + 2];
        int2 q3 = g_sn[e + 3];
        float2 t0 = __half22float2(tmp[(size_t)q0.x * 32 + lane]);
        float2 t1 = __half22float2(tmp[(size_t)q1.x * 32 + lane]);
        float2 t2 = __half22float2(tmp[(size_t)q2.x * 32 + lane]);
        float2 t3 = __half22float2(tmp[(size_t)q3.x * 32 + lane]);
        float w0 = __int_as_float(q0.y), w1 = __int_as_float(q1.y);
        float w2 = __int_as_float(q2.y), w3 = __int_as_float(q3.y);
        a0 += t0.x * w0; a1 += t0.y * w0;
        a0 += t1.x * w1; a1 += t1.y * w1;
        a0 += t2.x * w2; a1 += t2.y * w2;
        a0 += t3.x * w3; a1 += t3.y * w3;
    }
    for (; e < e1; e++) {
        int2 q = g_sn[e];
        float2 t = __half22float2(tmp[(size_t)q.x * 32 + lane]);
        float w = __int_as_float(q.y);
        a0 += t.x * w; a1 += t.y * w;
    }
    float2 bb = b1[lane];
    h[(size_t)i * 32 + lane] =
        __floats2half2_rn(fmaxf(a0 + bb.x, 0.f), fmaxf(a1 + bb.y, 0.f));
}

// ---------------- aggregation, layer 2 (F=16): 16 threads per node -----------
__global__ void k_agg2(const float* __restrict__ tmp,
                       const float* __restrict__ b2,
                       float* __restrict__ out, int n) {
    int i = (blockIdx.x * blockDim.x + threadIdx.x) >> 4;
    int l = threadIdx.x & 15;
    if (i >= n) return;
    float di = g_dinv[i];
    float a = tmp[(size_t)i * 16 + l] * di * di;

    int e1 = g_off[i];
    int e  = e1 - g_cnt[i];
    for (; e + 4 <= e1; e += 4) {
        int2 q0 = g_sn[e];
        int2 q1 = g_sn[e + 1];
        int2 q2 = g_sn[e + 2];
        int2 q3 = g_sn[e + 3];
        float t0 = tmp[(size_t)q0.x * 16 + l];
        float t1 = tmp[(size_t)q1.x * 16 + l];
        float t2 = tmp[(size_t)q2.x * 16 + l];
        float t3 = tmp[(size_t)q3.x * 16 + l];
        a += t0 * __int_as_float(q0.y);
        a += t1 * __int_as_float(q1.y);
        a += t2 * __int_as_float(q2.y);
        a += t3 * __int_as_float(q3.y);
    }
    for (; e < e1; e++) {
        int2 q = g_sn[e];
        a += tmp[(size_t)q.x * 16 + l] * __int_as_float(q.y);
    }
    out[(size_t)i * 16 + l] = a + b2[l];
}

// ---------------- launcher ---------------------------------------------------
extern "C" void kernel_launch(void* const* d_in, const int* in_sizes, int n_in,
                              void* d_out, int out_size) {
    const float* x  = (const float*)d_in[0];
    const void*  ei = d_in[1];
    const float* W1 = (const float*)d_in[2];
    const float* b1 = (const float*)d_in[3];
    const float* W2 = (const float*)d_in[4];
    const float* b2 = (const float*)d_in[5];
    float* out = (float*)d_out;

    const int n = in_sizes[0] / FH;
    const int E = in_sizes[1] / 2;

    __half2* tmp1h; cudaGetSymbolAddress((void**)&tmp1h, g_tmp1h);
    __half2* h;     cudaGetSymbolAddress((void**)&h,     g_h);
    float*   tmp2;  cudaGetSymbolAddress((void**)&tmp2,  g_tmp2);
    int*     cnt;   cudaGetSymbolAddress((void**)&cnt,   g_cnt);

    const int T  = 256;
    const int gE = (E + T - 1) / T;
    const int nb = (n + SCAN_T - 1) / SCAN_T;

    cudaMemsetAsync(cnt, 0, (size_t)(NN + 128) * sizeof(int));
    k_hist   <<<gE + 1, T>>>(ei, E, n, W1, W2);   // +1 block = weight prep
    k_scan   <<<nb, SCAN_T>>>(n);
    k_scatter<<<gE, T>>>(ei, E, n);

    // Layer 1
    k_gemm64_tc<<<(n + 127) / 128, 256>>>(x, tmp1h, n);
    k_agg1     <<<(n * 32 + T - 1) / T, T>>>(tmp1h, (const float2*)b1, h, n);

    // Layer 2
    k_gemm16_tc<<<(n + 127) / 128, 256>>>(h, tmp2, n);
    k_agg2     <<<(n * 16 + T - 1) / T, T>>>(tmp2, b2, out, n);

    (void)n_in; (void)out_size;
}

// round 9
// speedup vs baseline: 1.5614x; 1.0983x over previous
#include <cuda_runtime.h>
#include <cuda_fp16.h>
#include <cstdint>

#define NN 100000
#define NE 800000
#define FH 64
#define FO 16
#define SCAN_T 1024
#define G1_TILES 4          // tiles (64 rows) per gemm64 block

// ---------------- scratch ----------------------------------------------------
__device__ int     g_cnt[NN + 128];   // [0,NN): in-degree; [NN,..): lookback slots
__device__ int     g_off[NN];         // CSR offsets; AFTER scatter = end pointers
__device__ float   g_dinv[NN];
__device__ int2    g_sn[NE];          // CSR payload: (src, nrm bits)
__device__ __half2 g_tmp1h[(size_t)NN * 32];   // x @ W1, fp16
__device__ __half2 g_h[(size_t)NN * 32];       // relu(agg1)+b1, fp16
__device__ float   g_tmp2[(size_t)NN * FO];    // h @ W2, fp32
__device__ __half  g_w1t[64 * 64];    // W1^T fp16: [n][k]
__device__ __half  g_w2t[16 * 64];    // W2^T fp16: [n][k]

// ---------------- helpers ----------------------------------------------------
__device__ __forceinline__ uint32_t smem_u32(const void* p) {
    return (uint32_t)__cvta_generic_to_shared(p);
}
__device__ __forceinline__ void cp_async16(uint32_t dst, const void* src, int sz) {
    asm volatile("cp.async.ca.shared.global [%0], [%1], 16, %2;"
                 :: "r"(dst), "l"(src), "r"(sz));
}

// ---------------- per-block dtype detect (blockDim.x >= 256) -----------------
__device__ __forceinline__ int block_detect64(const void* edge, int n_nodes) {
    const long long* p = (const long long*)edge;
    long long v = p[threadIdx.x & 255];
    bool bad = (v < 0 || v >= (long long)n_nodes);
    return __syncthreads_or(bad ? 1 : 0) ? 0 : 1;
}

// ---------------- histogram + (last block) weight prep -----------------------
__global__ void k_hist(const void* edge, int E, int n_nodes,
                       const float* __restrict__ W1,
                       const float* __restrict__ W2) {
    if (blockIdx.x == gridDim.x - 1) {        // weight-prep block (concurrent)
        int tid = threadIdx.x;
        for (int i = tid; i < 64 * 64; i += 256) {
            int k = i >> 6, nn = i & 63;      // W1[k][n] -> w1t[n][k]
            g_w1t[nn * 64 + k] = __float2half_rn(W1[i]);
        }
        for (int i = tid; i < 64 * 16; i += 256) {
            int k = i >> 4, nn = i & 15;      // W2[k][n] -> w2t[n][k]
            g_w2t[nn * 64 + k] = __float2half_rn(W2[i]);
        }
        return;
    }
    int is64 = block_detect64(edge, n_nodes);
    int e = blockIdx.x * blockDim.x + threadIdx.x;
    if (e >= E) return;
    int c = is64 ? (int)((const long long*)edge)[e + E]
                 : ((const int*)edge)[e + E];
    atomicAdd(&g_cnt[c], 1);
}

// ---------------- fused scan (deadlock-free lookback) + dinv -----------------
__global__ void k_scan(int n) {
    __shared__ int s[SCAN_T];
    __shared__ int s_pref;
    int b = blockIdx.x, t = threadIdx.x;
    int i = b * SCAN_T + t;
    int val = 0;
    if (i < n) {
        val = g_cnt[i];
        g_dinv[i] = rsqrtf((float)val + 1.0f);   // +1 self loop
    }
    s[t] = val;
    __syncthreads();
    for (int d = 1; d < SCAN_T; d <<= 1) {
        int add = (t >= d) ? s[t - d] : 0;
        __syncthreads();
        s[t] += add;
        __syncthreads();
    }
    if (t == SCAN_T - 1) atomicExch(&g_cnt[NN + b], s[t] + 1);   // publish first
    if (t == 0) s_pref = 0;
    __syncthreads();
    if (t < b) {
        int v;
        do { v = atomicAdd(&g_cnt[NN + t], 0); } while (v == 0);
        atomicAdd(&s_pref, v - 1);
    }
    __syncthreads();
    if (i < n) g_off[i] = s[t] - val + s_pref;
}

// ---------------- counting-sort scatter + lookback-slot cleanup --------------
__global__ void k_scatter(const void* edge, int E, int n_nodes) {
    if (blockIdx.x == 0 && threadIdx.x < 128)
        g_cnt[NN + threadIdx.x] = 0;          // reset lookback slots for next call
    int is64 = block_detect64(edge, n_nodes);
    int e = blockIdx.x * blockDim.x + threadIdx.x;
    if (e >= E) return;
    int r, c;
    if (is64) {
        const long long* p = (const long long*)edge;
        r = (int)p[e]; c = (int)p[e + E];
    } else {
        const int* p = (const int*)edge;
        r = p[e]; c = p[e + E];
    }
    float nr = g_dinv[r] * g_dinv[c];
    int pos = atomicAdd(&g_off[c], 1);
    g_sn[pos] = make_int2(r, __float_as_int(nr));
}

// ---------------- GEMM1 (TC, pipelined): tmp1h = fp16(x @ W1) ----------------
// 256 thr / 8 warps. Tile = 64 rows x 64 cols; G1_TILES tiles per block with
// double-buffered cp.async fp32 staging. Warp = (q = col-half, w2 = row-group).
__global__ void k_gemm64_tc(const float* __restrict__ A,
                            __half2* __restrict__ outh, int n) {
    __shared__ float  Xf[2][64][72];   // fp32 X tiles (reused for fp16 C staging)
    __shared__ __half Wts[64][72];     // W1^T [n][k]

    int tid  = threadIdx.x;
    int lane = tid & 31;
    int warp = tid >> 5;
    int q  = warp >> 2;                // 0/1: n-cols [q*32, q*32+32)
    int w2 = warp & 3;                 // row group: rows [w2*16, w2*16+16)
    int g = lane >> 2, t = lane & 3;
    int row0 = w2 * 16;

    // stage Wt (pre-transposed fp16): 512 x uint4
    for (int idx = tid; idx < 512; idx += 256) {
        uint4 v = *(const uint4*)&g_w1t[idx * 8];
        *(uint4*)&Wts[idx >> 3][(idx & 7) * 8] = v;
    }

    int tile0 = blockIdx.x * G1_TILES;

    // prefetch tile 0
    {
        int rb = tile0 * 64;
#pragma unroll
        for (int j = 0; j < 4; j++) {
            int idx = tid + j * 256;
            int r = idx >> 4, k4 = (idx & 15) << 2;
            int gr = rb + r;
            cp_async16(smem_u32(&Xf[0][r][k4]), A + (size_t)gr * 64 + k4,
                       (gr < n) ? 16 : 0);
        }
        asm volatile("cp.async.commit_group;");
    }

    for (int tt = 0; tt < G1_TILES; tt++) {
        int buf = tt & 1;
        int rb  = (tile0 + tt) * 64;

        if (tt + 1 < G1_TILES) {
            int rb2 = rb + 64;
#pragma unroll
            for (int j = 0; j < 4; j++) {
                int idx = tid + j * 256;
                int r = idx >> 4, k4 = (idx & 15) << 2;
                int gr = rb2 + r;
                cp_async16(smem_u32(&Xf[buf ^ 1][r][k4]), A + (size_t)gr * 64 + k4,
                           (gr < n) ? 16 : 0);
            }
            asm volatile("cp.async.commit_group;");
            asm volatile("cp.async.wait_group 1;");
        } else {
            asm volatile("cp.async.wait_group 0;");
        }
        __syncthreads();

        float acc[4][4];
#pragma unroll
        for (int j = 0; j < 4; j++)
#pragma unroll
            for (int m = 0; m < 4; m++) acc[j][m] = 0.f;

#pragma unroll
        for (int k0 = 0; k0 < 64; k0 += 16) {
            float2 f0 = *(const float2*)&Xf[buf][row0 + g    ][k0 + 2 * t];
            float2 f1 = *(const float2*)&Xf[buf][row0 + g + 8][k0 + 2 * t];
            float2 f2 = *(const float2*)&Xf[buf][row0 + g    ][k0 + 2 * t + 8];
            float2 f3 = *(const float2*)&Xf[buf][row0 + g + 8][k0 + 2 * t + 8];
            __half2 h0 = __floats2half2_rn(f0.x, f0.y);
            __half2 h1 = __floats2half2_rn(f1.x, f1.y);
            __half2 h2 = __floats2half2_rn(f2.x, f2.y);
            __half2 h3 = __floats2half2_rn(f3.x, f3.y);
            unsigned ra0 = *(unsigned*)&h0, ra1 = *(unsigned*)&h1;
            unsigned ra2 = *(unsigned*)&h2, ra3 = *(unsigned*)&h3;
#pragma unroll
            for (int j = 0; j < 4; j++) {
                int nt = q * 4 + j;
                unsigned rb0 = *(const unsigned*)&Wts[nt * 8 + g][k0 + 2 * t];
                unsigned rb1 = *(const unsigned*)&Wts[nt * 8 + g][k0 + 2 * t + 8];
                asm volatile(
                    "mma.sync.aligned.m16n8k16.row.col.f32.f16.f16.f32 "
                    "{%0,%1,%2,%3}, {%4,%5,%6,%7}, {%8,%9}, {%0,%1,%2,%3};"
                    : "+f"(acc[j][0]), "+f"(acc[j][1]),
                      "+f"(acc[j][2]), "+f"(acc[j][3])
                    : "r"(ra0), "r"(ra1), "r"(ra2), "r"(ra3),
                      "r"(rb0), "r"(rb1));
            }
        }
        __syncthreads();   // all A reads done before C overwrites the buffer

        // stage C fp16 into Xf[buf] (word col = nt*4+t, rows row0+g / +8)
#pragma unroll
        for (int j = 0; j < 4; j++) {
            int nt = q * 4 + j;
            __half2 c0 = __floats2half2_rn(acc[j][0], acc[j][1]);
            __half2 c1 = __floats2half2_rn(acc[j][2], acc[j][3]);
            *(__half2*)&Xf[buf][row0 + g    ][nt * 4 + t] = c0;
            *(__half2*)&Xf[buf][row0 + g + 8][nt * 4 + t] = c1;
        }
        __syncthreads();

        // copy out: 512 uint4 (64 rows x 8 x 16B), fully coalesced
        for (int idx = tid; idx < 512; idx += 256) {
            int r = idx >> 3, c = idx & 7;
            int gr = rb + r;
            if (gr < n) {
                uint4 v = *(const uint4*)&Xf[buf][r][c * 4];
                *(uint4*)&outh[(size_t)gr * 32 + c * 4] = v;
            }
        }
        __syncthreads();   // buffer free before next cp.async targets it
    }
}

// ---------------- GEMM2 (TC): tmp2[n,16]f32 = h[n,64]fp16 @ W2 ---------------
__global__ void k_gemm16_tc(const __half2* __restrict__ Ah,
                            float* __restrict__ out, int n) {
    __shared__ __half Xs[128][72];
    __shared__ __half Wts[16][72];

    int tid  = threadIdx.x;
    int base = blockIdx.x * 128;
    int lane = tid & 31;
    int warp = tid >> 5;
    int g = lane >> 2, t = lane & 3;
    int row0 = warp * 16;

    if (tid < 128) {
        uint4 v = *(const uint4*)&g_w2t[tid * 8];
        *(uint4*)&Wts[tid >> 3][(tid & 7) * 8] = v;
    }
    for (int idx = tid; idx < 1024; idx += 256) {
        int r = idx >> 3, c8 = idx & 7;
        uint4 v = make_uint4(0u, 0u, 0u, 0u);
        int gr = base + r;
        if (gr < n) v = *(const uint4*)&Ah[(size_t)gr * 32 + c8 * 4];
        *(uint4*)&Xs[r][c8 * 8] = v;
    }
    __syncthreads();

    float acc[2][4];
#pragma unroll
    for (int nt = 0; nt < 2; nt++)
#pragma unroll
        for (int j = 0; j < 4; j++) acc[nt][j] = 0.f;

#pragma unroll
    for (int k0 = 0; k0 < 64; k0 += 16) {
        unsigned ra0 = *(const unsigned*)&Xs[row0 + g    ][k0 + 2 * t];
        unsigned ra1 = *(const unsigned*)&Xs[row0 + g + 8][k0 + 2 * t];
        unsigned ra2 = *(const unsigned*)&Xs[row0 + g    ][k0 + 2 * t + 8];
        unsigned ra3 = *(const unsigned*)&Xs[row0 + g + 8][k0 + 2 * t + 8];
#pragma unroll
        for (int nt = 0; nt < 2; nt++) {
            unsigned rb0 = *(const unsigned*)&Wts[nt * 8 + g][k0 + 2 * t];
            unsigned rb1 = *(const unsigned*)&Wts[nt * 8 + g][k0 + 2 * t + 8];
            asm volatile(
                "mma.sync.aligned.m16n8k16.row.col.f32.f16.f16.f32 "
                "{%0,%1,%2,%3}, {%4,%5,%6,%7}, {%8,%9}, {%0,%1,%2,%3};"
                : "+f"(acc[nt][0]), "+f"(acc[nt][1]),
                  "+f"(acc[nt][2]), "+f"(acc[nt][3])
                : "r"(ra0), "r"(ra1), "r"(ra2), "r"(ra3),
                  "r"(rb0), "r"(rb1));
        }
    }

#pragma unroll
    for (int nt = 0; nt < 2; nt++) {
        int c0 = nt * 8 + 2 * t;
        int gr0 = base + row0 + g;
        int gr1 = gr0 + 8;
        if (gr0 < n)
            *(float2*)&out[(size_t)gr0 * 16 + c0] = make_float2(acc[nt][0], acc[nt][1]);
        if (gr1 < n)
            *(float2*)&out[(size_t)gr1 * 16 + c0] = make_float2(acc[nt][2], acc[nt][3]);
    }
}

// ---------------- aggregation, layer 1 (F=64 fp16): 16 threads per node ------
__global__ void k_agg1(const __half2* __restrict__ tmp,
                       const float4* __restrict__ b1,
                       __half2* __restrict__ h, int n) {
    int i = (blockIdx.x * blockDim.x + threadIdx.x) >> 4;
    int l = threadIdx.x & 15;          // lane owns half2 cols {2l, 2l+1}
    if (i >= n) return;
    float di = g_dinv[i];
    float ws = di * di;
    uint2 raw = *(const uint2*)&tmp[(size_t)i * 32 + 2 * l];
    float2 v0 = __half22float2(*(__half2*)&raw.x);
    float2 v1 = __half22float2(*(__half2*)&raw.y);
    float a0 = v0.x * ws, a1 = v0.y * ws, a2 = v1.x * ws, a3 = v1.y * ws;

    int e1 = g_off[i];
    int e  = e1 - g_cnt[i];
    for (; e + 4 <= e1; e += 4) {
        int2 q0 = g_sn[e];
        int2 q1 = g_sn[e + 1];
        int2 q2 = g_sn[e + 2];
        int2 q3 = g_sn[e + 3];
        uint2 r0 = *(const uint2*)&tmp[(size_t)q0.x * 32 + 2 * l];
        uint2 r1 = *(const uint2*)&tmp[(size_t)q1.x * 32 + 2 * l];
        uint2 r2 = *(const uint2*)&tmp[(size_t)q2.x * 32 + 2 * l];
        uint2 r3 = *(const uint2*)&tmp[(size_t)q3.x * 32 + 2 * l];
        float w0 = __int_as_float(q0.y), w1 = __int_as_float(q1.y);
        float w2 = __int_as_float(q2.y), w3 = __int_as_float(q3.y);
        float2 p;
        p = __half22float2(*(__half2*)&r0.x); a0 += p.x * w0; a1 += p.y * w0;
        p = __half22float2(*(__half2*)&r0.y); a2 += p.x * w0; a3 += p.y * w0;
        p = __half22float2(*(__half2*)&r1.x); a0 += p.x * w1; a1 += p.y * w1;
        p = __half22float2(*(__half2*)&r1.y); a2 += p.x * w1; a3 += p.y * w1;
        p = __half22float2(*(__half2*)&r2.x); a0 += p.x * w2; a1 += p.y * w2;
        p = __half22float2(*(__half2*)&r2.y); a2 += p.x * w2; a3 += p.y * w2;
        p = __half22float2(*(__half2*)&r3.x); a0 += p.x * w3; a1 += p.y * w3;
        p = __half22float2(*(__half2*)&r3.y); a2 += p.x * w3; a3 += p.y * w3;
    }
    for (; e < e1; e++) {
        int2 qq = g_sn[e];
        uint2 rr = *(const uint2*)&tmp[(size_t)qq.x * 32 + 2 * l];
        float w = __int_as_float(qq.y);
        float2 p;
        p = __half22float2(*(__half2*)&rr.x); a0 += p.x * w; a1 += p.y * w;
        p = __half22float2(*(__half2*)&rr.y); a2 += p.x * w; a3 += p.y * w;
    }
    float4 bb = b1[l];
    __half2 o0 = __floats2half2_rn(fmaxf(a0 + bb.x, 0.f), fmaxf(a1 + bb.y, 0.f));
    __half2 o1 = __floats2half2_rn(fmaxf(a2 + bb.z, 0.f), fmaxf(a3 + bb.w, 0.f));
    uint2 ov;
    ov.x = *(unsigned*)&o0; ov.y = *(unsigned*)&o1;
    *(uint2*)&h[(size_t)i * 32 + 2 * l] = ov;
}

// ---------------- aggregation, layer 2 (F=16) + cnt self-clean ---------------
__global__ void k_agg2(const float* __restrict__ tmp,
                       const float* __restrict__ b2,
                       float* __restrict__ out, int n) {
    int i = (blockIdx.x * blockDim.x + threadIdx.x) >> 4;
    int l = threadIdx.x & 15;
    if (i >= n) return;
    float di = g_dinv[i];
    float a = tmp[(size_t)i * 16 + l] * di * di;

    int e1 = g_off[i];
    int cnt = g_cnt[i];
    int e  = e1 - cnt;
    for (; e + 4 <= e1; e += 4) {
        int2 q0 = g_sn[e];
        int2 q1 = g_sn[e + 1];
        int2 q2 = g_sn[e + 2];
        int2 q3 = g_sn[e + 3];
        float t0 = tmp[(size_t)q0.x * 16 + l];
        float t1 = tmp[(size_t)q1.x * 16 + l];
        float t2 = tmp[(size_t)q2.x * 16 + l];
        float t3 = tmp[(size_t)q3.x * 16 + l];
        a += t0 * __int_as_float(q0.y);
        a += t1 * __int_as_float(q1.y);
        a += t2 * __int_as_float(q2.y);
        a += t3 * __int_as_float(q3.y);
    }
    for (; e < e1; e++) {
        int2 q = g_sn[e];
        a += tmp[(size_t)q.x * 16 + l] * __int_as_float(q.y);
    }
    out[(size_t)i * 16 + l] = a + b2[l];
    if (l == 0) g_cnt[i] = 0;          // restore pre-call invariant (cnt == 0)
}

// ---------------- launcher ---------------------------------------------------
extern "C" void kernel_launch(void* const* d_in, const int* in_sizes, int n_in,
                              void* d_out, int out_size) {
    const float* x  = (const float*)d_in[0];
    const void*  ei = d_in[1];
    const float* W1 = (const float*)d_in[2];
    const float* b1 = (const float*)d_in[3];
    const float* W2 = (const float*)d_in[4];
    const float* b2 = (const float*)d_in[5];
    float* out = (float*)d_out;

    const int n = in_sizes[0] / FH;
    const int E = in_sizes[1] / 2;

    __half2* tmp1h; cudaGetSymbolAddress((void**)&tmp1h, g_tmp1h);
    __half2* h;     cudaGetSymbolAddress((void**)&h,     g_h);
    float*   tmp2;  cudaGetSymbolAddress((void**)&tmp2,  g_tmp2);

    const int T  = 256;
    const int gE = (E + T - 1) / T;
    const int nb = (n + SCAN_T - 1) / SCAN_T;
    const int tiles = (n + 63) / 64;
    const int g1b = (tiles + G1_TILES - 1) / G1_TILES;

    k_hist   <<<gE + 1, T>>>(ei, E, n, W1, W2);   // +1 block = weight prep
    k_scan   <<<nb, SCAN_T>>>(n);
    k_scatter<<<gE, T>>>(ei, E, n);

    // Layer 1
    k_gemm64_tc<<<g1b, 256>>>(x, tmp1h, n);
    k_agg1     <<<(n * 16 + T - 1) / T, T>>>(tmp1h, (const float4*)b1, h, n);

    // Layer 2
    k_gemm16_tc<<<(n + 127) / 128, 256>>>(h, tmp2, n);
    k_agg2     <<<(n * 16 + T - 1) / T, T>>>(tmp2, b2, out, n);

    (void)n_in; (void)out_size;
}

// round 11
// speedup vs baseline: 1.6770x; 1.0741x over previous
#include <cuda_runtime.h>
#include <cuda_fp16.h>
#include <cstdint>

#define NN 100000
#define NE 800000
#define FH 64
#define FO 16
#define SCAN_T 1024
#define G1_TILES 2          // 64-row tiles per gemm64 block

// ---------------- scratch ----------------------------------------------------
__device__ int     g_cnt[NN + 128];   // [0,NN): in-degree; [NN,..): lookback slots
__device__ int     g_off[NN];         // CSR offsets; AFTER scatter = end pointers
__device__ float   g_dinv[NN];
__device__ int2    g_rc[NE];          // converted (src,dst) per edge
__device__ int2    g_sn[NE];          // CSR payload: (src, nrm bits)
__device__ __half2 g_tmp1h[(size_t)NN * 32];   // x @ W1, fp16
__device__ float   g_tmp2[(size_t)NN * FO];    // gcn1(h) @ W2, fp32
__device__ __half  g_w1t[64 * 64];    // W1^T fp16: [n][k]
__device__ __half  g_w2t[16 * 64];    // W2^T fp16: [n][k]

// ---------------- helpers ----------------------------------------------------
__device__ __forceinline__ uint32_t smem_u32(const void* p) {
    return (uint32_t)__cvta_generic_to_shared(p);
}
__device__ __forceinline__ void cp_async16(uint32_t dst, const void* src, int sz) {
    asm volatile("cp.async.ca.shared.global [%0], [%1], 16, %2;"
                 :: "r"(dst), "l"(src), "r"(sz));
}
__device__ __forceinline__ int block_detect64(const void* edge, int n_nodes) {
    const long long* p = (const long long*)edge;
    long long v = p[threadIdx.x & 255];
    bool bad = (v < 0 || v >= (long long)n_nodes);
    return __syncthreads_or(bad ? 1 : 0) ? 0 : 1;
}

// ---------------- hist + edge convert + (last block) weight prep -------------
__global__ void k_hist(const void* edge, int E, int n_nodes,
                       const float* __restrict__ W1,
                       const float* __restrict__ W2) {
    if (blockIdx.x == gridDim.x - 1) {        // weight-prep block (concurrent)
        int tid = threadIdx.x;
        for (int i = tid; i < 64 * 64; i += 256) {
            int k = i >> 6, nn = i & 63;      // W1[k][n] -> w1t[n][k]
            g_w1t[nn * 64 + k] = __float2half_rn(W1[i]);
        }
        for (int i = tid; i < 64 * 16; i += 256) {
            int k = i >> 4, nn = i & 15;      // W2[k][n] -> w2t[n][k]
            g_w2t[nn * 64 + k] = __float2half_rn(W2[i]);
        }
        return;
    }
    int is64 = block_detect64(edge, n_nodes);
    int e = blockIdx.x * blockDim.x + threadIdx.x;
    if (e >= E) return;
    int r, c;
    if (is64) {
        const long long* p = (const long long*)edge;
        r = (int)p[e]; c = (int)p[e + E];
    } else {
        const int* p = (const int*)edge;
        r = p[e]; c = p[e + E];
    }
    g_rc[e] = make_int2(r, c);
    atomicAdd(&g_cnt[c], 1);
}

// ---------------- fused scan (deadlock-free lookback) + dinv -----------------
__global__ void k_scan(int n) {
    __shared__ int s[SCAN_T];
    __shared__ int s_pref;
    int b = blockIdx.x, t = threadIdx.x;
    int i = b * SCAN_T + t;
    int val = 0;
    if (i < n) {
        val = g_cnt[i];
        g_dinv[i] = rsqrtf((float)val + 1.0f);   // +1 self loop
    }
    s[t] = val;
    __syncthreads();
    for (int d = 1; d < SCAN_T; d <<= 1) {
        int add = (t >= d) ? s[t - d] : 0;
        __syncthreads();
        s[t] += add;
        __syncthreads();
    }
    if (t == SCAN_T - 1) atomicExch(&g_cnt[NN + b], s[t] + 1);   // publish first
    if (t == 0) s_pref = 0;
    __syncthreads();
    if (t < b) {
        int v;
        do { v = atomicAdd(&g_cnt[NN + t], 0); } while (v == 0);
        atomicAdd(&s_pref, v - 1);
    }
    __syncthreads();
    if (i < n) g_off[i] = s[t] - val + s_pref;
}

// ---------------- counting-sort scatter + lookback-slot cleanup --------------
__global__ void k_scatter(int E) {
    if (blockIdx.x == 0 && threadIdx.x < 128)
        g_cnt[NN + threadIdx.x] = 0;          // reset lookback slots for next call
    int e = blockIdx.x * blockDim.x + threadIdx.x;
    if (e >= E) return;
    int2 rc = g_rc[e];
    float nr = g_dinv[rc.x] * g_dinv[rc.y];
    int pos = atomicAdd(&g_off[rc.y], 1);
    g_sn[pos] = make_int2(rc.x, __float_as_int(nr));
}

// ---------------- GEMM1 (TC, pipelined): tmp1h = fp16(x @ W1) ----------------
__global__ void k_gemm64_tc(const float* __restrict__ A,
                            __half2* __restrict__ outh, int n) {
    __shared__ float  Xf[2][64][72];   // fp32 X tiles (reused for fp16 C staging)
    __shared__ __half Wts[64][72];     // W1^T [n][k]

    int tid  = threadIdx.x;
    int lane = tid & 31;
    int warp = tid >> 5;
    int q  = warp >> 2;                // col-half
    int w2 = warp & 3;                 // row group
    int g = lane >> 2, t = lane & 3;
    int row0 = w2 * 16;

    for (int idx = tid; idx < 512; idx += 256) {
        uint4 v = *(const uint4*)&g_w1t[idx * 8];
        *(uint4*)&Wts[idx >> 3][(idx & 7) * 8] = v;
    }

    int tile0 = blockIdx.x * G1_TILES;
    {
        int rb = tile0 * 64;
#pragma unroll
        for (int j = 0; j < 4; j++) {
            int idx = tid + j * 256;
            int r = idx >> 4, k4 = (idx & 15) << 2;
            int gr = rb + r;
            cp_async16(smem_u32(&Xf[0][r][k4]), A + (size_t)gr * 64 + k4,
                       (gr < n) ? 16 : 0);
        }
        asm volatile("cp.async.commit_group;");
    }

    for (int tt = 0; tt < G1_TILES; tt++) {
        int buf = tt & 1;
        int rb  = (tile0 + tt) * 64;

        if (tt + 1 < G1_TILES) {
            int rb2 = rb + 64;
#pragma unroll
            for (int j = 0; j < 4; j++) {
                int idx = tid + j * 256;
                int r = idx >> 4, k4 = (idx & 15) << 2;
                int gr = rb2 + r;
                cp_async16(smem_u32(&Xf[buf ^ 1][r][k4]), A + (size_t)gr * 64 + k4,
                           (gr < n) ? 16 : 0);
            }
            asm volatile("cp.async.commit_group;");
            asm volatile("cp.async.wait_group 1;");
        } else {
            asm volatile("cp.async.wait_group 0;");
        }
        __syncthreads();

        float acc[4][4];
#pragma unroll
        for (int j = 0; j < 4; j++)
#pragma unroll
            for (int m = 0; m < 4; m++) acc[j][m] = 0.f;

#pragma unroll
        for (int k0 = 0; k0 < 64; k0 += 16) {
            float2 f0 = *(const float2*)&Xf[buf][row0 + g    ][k0 + 2 * t];
            float2 f1 = *(const float2*)&Xf[buf][row0 + g + 8][k0 + 2 * t];
            float2 f2 = *(const float2*)&Xf[buf][row0 + g    ][k0 + 2 * t + 8];
            float2 f3 = *(const float2*)&Xf[buf][row0 + g + 8][k0 + 2 * t + 8];
            __half2 h0 = __floats2half2_rn(f0.x, f0.y);
            __half2 h1 = __floats2half2_rn(f1.x, f1.y);
            __half2 h2 = __floats2half2_rn(f2.x, f2.y);
            __half2 h3 = __floats2half2_rn(f3.x, f3.y);
            unsigned ra0 = *(unsigned*)&h0, ra1 = *(unsigned*)&h1;
            unsigned ra2 = *(unsigned*)&h2, ra3 = *(unsigned*)&h3;
#pragma unroll
            for (int j = 0; j < 4; j++) {
                int nt = q * 4 + j;
                unsigned rb0 = *(const unsigned*)&Wts[nt * 8 + g][k0 + 2 * t];
                unsigned rb1 = *(const unsigned*)&Wts[nt * 8 + g][k0 + 2 * t + 8];
                asm volatile(
                    "mma.sync.aligned.m16n8k16.row.col.f32.f16.f16.f32 "
                    "{%0,%1,%2,%3}, {%4,%5,%6,%7}, {%8,%9}, {%0,%1,%2,%3};"
                    : "+f"(acc[j][0]), "+f"(acc[j][1]),
                      "+f"(acc[j][2]), "+f"(acc[j][3])
                    : "r"(ra0), "r"(ra1), "r"(ra2), "r"(ra3),
                      "r"(rb0), "r"(rb1));
            }
        }
        __syncthreads();

#pragma unroll
        for (int j = 0; j < 4; j++) {
            int nt = q * 4 + j;
            __half2 c0 = __floats2half2_rn(acc[j][0], acc[j][1]);
            __half2 c1 = __floats2half2_rn(acc[j][2], acc[j][3]);
            *(__half2*)&Xf[buf][row0 + g    ][nt * 4 + t] = c0;
            *(__half2*)&Xf[buf][row0 + g + 8][nt * 4 + t] = c1;
        }
        __syncthreads();

        for (int idx = tid; idx < 512; idx += 256) {
            int r = idx >> 3, c = idx & 7;
            int gr = rb + r;
            if (gr < n) {
                uint4 v = *(const uint4*)&Xf[buf][r][c * 4];
                *(uint4*)&outh[(size_t)gr * 32 + c * 4] = v;
            }
        }
        __syncthreads();
    }
}

// ---------------- fused layer-2a: agg1 (into smem) + gemm16 ------------------
// 256 thr; tile = 128 nodes. Phase 1: 8 thr/node aggregate relu(gcn1) as fp16
// into Hs. Phase 2: 8 warps MMA Hs @ W2t -> tmp2 (fp32).
__global__ void k_layer2a(const __half2* __restrict__ tmp,
                          const float4* __restrict__ b1,
                          float* __restrict__ out, int n) {
    __shared__ __half Hs[128][72];
    __shared__ __half Wts[16][72];

    int tid  = threadIdx.x;
    int base = blockIdx.x * 128;
    int lane = tid & 31;
    int warp = tid >> 5;
    int g = lane >> 2, t = lane & 3;
    int l = tid & 7;                     // lane-in-node: half2 cols [4l, 4l+4)

    if (tid < 128) {
        uint4 v = *(const uint4*)&g_w2t[tid * 8];
        *(uint4*)&Wts[tid >> 3][(tid & 7) * 8] = v;
    }

    // Phase 1: aggregate 128 nodes, 32 nodes per batch (8 threads per node)
#pragma unroll
    for (int batch = 0; batch < 4; batch++) {
        int node = base + batch * 32 + (tid >> 3);
        float a0 = 0.f, a1 = 0.f, a2 = 0.f, a3 = 0.f,
              a4 = 0.f, a5 = 0.f, a6 = 0.f, a7 = 0.f;
        if (node < n) {
            float di = g_dinv[node];
            float ws = di * di;
            uint4 raw = *(const uint4*)&tmp[(size_t)node * 32 + 4 * l];
            float2 p;
            p = __half22float2(*(__half2*)&raw.x); a0 = p.x * ws; a1 = p.y * ws;
            p = __half22float2(*(__half2*)&raw.y); a2 = p.x * ws; a3 = p.y * ws;
            p = __half22float2(*(__half2*)&raw.z); a4 = p.x * ws; a5 = p.y * ws;
            p = __half22float2(*(__half2*)&raw.w); a6 = p.x * ws; a7 = p.y * ws;

            int e1 = g_off[node];
            int e  = e1 - g_cnt[node];
            for (; e + 2 <= e1; e += 2) {
                int2 q0 = g_sn[e];
                int2 q1 = g_sn[e + 1];
                uint4 r0 = *(const uint4*)&tmp[(size_t)q0.x * 32 + 4 * l];
                uint4 r1 = *(const uint4*)&tmp[(size_t)q1.x * 32 + 4 * l];
                float w0 = __int_as_float(q0.y), w1 = __int_as_float(q1.y);
                p = __half22float2(*(__half2*)&r0.x); a0 += p.x * w0; a1 += p.y * w0;
                p = __half22float2(*(__half2*)&r0.y); a2 += p.x * w0; a3 += p.y * w0;
                p = __half22float2(*(__half2*)&r0.z); a4 += p.x * w0; a5 += p.y * w0;
                p = __half22float2(*(__half2*)&r0.w); a6 += p.x * w0; a7 += p.y * w0;
                p = __half22float2(*(__half2*)&r1.x); a0 += p.x * w1; a1 += p.y * w1;
                p = __half22float2(*(__half2*)&r1.y); a2 += p.x * w1; a3 += p.y * w1;
                p = __half22float2(*(__half2*)&r1.z); a4 += p.x * w1; a5 += p.y * w1;
                p = __half22float2(*(__half2*)&r1.w); a6 += p.x * w1; a7 += p.y * w1;
            }
            if (e < e1) {
                int2 q0 = g_sn[e];
                uint4 r0 = *(const uint4*)&tmp[(size_t)q0.x * 32 + 4 * l];
                float w0 = __int_as_float(q0.y);
                p = __half22float2(*(__half2*)&r0.x); a0 += p.x * w0; a1 += p.y * w0;
                p = __half22float2(*(__half2*)&r0.y); a2 += p.x * w0; a3 += p.y * w0;
                p = __half22float2(*(__half2*)&r0.z); a4 += p.x * w0; a5 += p.y * w0;
                p = __half22float2(*(__half2*)&r0.w); a6 += p.x * w0; a7 += p.y * w0;
            }
            float4 bb0 = b1[2 * l];
            float4 bb1 = b1[2 * l + 1];
            a0 = fmaxf(a0 + bb0.x, 0.f); a1 = fmaxf(a1 + bb0.y, 0.f);
            a2 = fmaxf(a2 + bb0.z, 0.f); a3 = fmaxf(a3 + bb0.w, 0.f);
            a4 = fmaxf(a4 + bb1.x, 0.f); a5 = fmaxf(a5 + bb1.y, 0.f);
            a6 = fmaxf(a6 + bb1.z, 0.f); a7 = fmaxf(a7 + bb1.w, 0.f);
        }
        __half2 o0 = __floats2half2_rn(a0, a1);
        __half2 o1 = __floats2half2_rn(a2, a3);
        __half2 o2 = __floats2half2_rn(a4, a5);
        __half2 o3 = __floats2half2_rn(a6, a7);
        uint4 ov;
        ov.x = *(unsigned*)&o0; ov.y = *(unsigned*)&o1;
        ov.z = *(unsigned*)&o2; ov.w = *(unsigned*)&o3;
        *(uint4*)&Hs[batch * 32 + (tid >> 3)][l * 8] = ov;
    }
    __syncthreads();

    // Phase 2: MMA 128x16 = Hs @ W2t
    int row0 = warp * 16;
    float acc[2][4];
#pragma unroll
    for (int nt = 0; nt < 2; nt++)
#pragma unroll
        for (int j = 0; j < 4; j++) acc[nt][j] = 0.f;

#pragma unroll
    for (int k0 = 0; k0 < 64; k0 += 16) {
        unsigned ra0 = *(const unsigned*)&Hs[row0 + g    ][k0 + 2 * t];
        unsigned ra1 = *(const unsigned*)&Hs[row0 + g + 8][k0 + 2 * t];
        unsigned ra2 = *(const unsigned*)&Hs[row0 + g    ][k0 + 2 * t + 8];
        unsigned ra3 = *(const unsigned*)&Hs[row0 + g + 8][k0 + 2 * t + 8];
#pragma unroll
        for (int nt = 0; nt < 2; nt++) {
            unsigned rb0 = *(const unsigned*)&Wts[nt * 8 + g][k0 + 2 * t];
            unsigned rb1 = *(const unsigned*)&Wts[nt * 8 + g][k0 + 2 * t + 8];
            asm volatile(
                "mma.sync.aligned.m16n8k16.row.col.f32.f16.f16.f32 "
                "{%0,%1,%2,%3}, {%4,%5,%6,%7}, {%8,%9}, {%0,%1,%2,%3};"
                : "+f"(acc[nt][0]), "+f"(acc[nt][1]),
                  "+f"(acc[nt][2]), "+f"(acc[nt][3])
                : "r"(ra0), "r"(ra1), "r"(ra2), "r"(ra3),
                  "r"(rb0), "r"(rb1));
        }
    }

#pragma unroll
    for (int nt = 0; nt < 2; nt++) {
        int c0 = nt * 8 + 2 * t;
        int gr0 = base + row0 + g;
        int gr1 = gr0 + 8;
        if (gr0 < n)
            *(float2*)&out[(size_t)gr0 * 16 + c0] = make_float2(acc[nt][0], acc[nt][1]);
        if (gr1 < n)
            *(float2*)&out[(size_t)gr1 * 16 + c0] = make_float2(acc[nt][2], acc[nt][3]);
    }
}

// ---------------- aggregation, layer 2 (F=16) + cnt self-clean ---------------
__global__ void k_agg2(const float* __restrict__ tmp,
                       const float* __restrict__ b2,
                       float* __restrict__ out, int n) {
    int i = (blockIdx.x * blockDim.x + threadIdx.x) >> 4;
    int l = threadIdx.x & 15;
    if (i >= n) return;
    float di = g_dinv[i];
    float a = tmp[(size_t)i * 16 + l] * di * di;

    int e1 = g_off[i];
    int cnt = g_cnt[i];
    int e  = e1 - cnt;
    for (; e + 4 <= e1; e += 4) {
        int2 q0 = g_sn[e];
        int2 q1 = g_sn[e + 1];
        int2 q2 = g_sn[e + 2];
        int2 q3 = g_sn[e + 3];
        float t0 = tmp[(size_t)q0.x * 16 + l];
        float t1 = tmp[(size_t)q1.x * 16 + l];
        float t2 = tmp[(size_t)q2.x * 16 + l];
        float t3 = tmp[(size_t)q3.x * 16 + l];
        a += t0 * __int_as_float(q0.y);
        a += t1 * __int_as_float(q1.y);
        a += t2 * __int_as_float(q2.y);
        a += t3 * __int_as_float(q3.y);
    }
    for (; e < e1; e++) {
        int2 q = g_sn[e];
        a += tmp[(size_t)q.x * 16 + l] * __int_as_float(q.y);
    }
    out[(size_t)i * 16 + l] = a + b2[l];
    if (l == 0) g_cnt[i] = 0;          // restore pre-call invariant (cnt == 0)
}

// ---------------- launcher ---------------------------------------------------
extern "C" void kernel_launch(void* const* d_in, const int* in_sizes, int n_in,
                              void* d_out, int out_size) {
    const float* x  = (const float*)d_in[0];
    const void*  ei = d_in[1];
    const float* W1 = (const float*)d_in[2];
    const float* b1 = (const float*)d_in[3];
    const float* W2 = (const float*)d_in[4];
    const float* b2 = (const float*)d_in[5];
    float* out = (float*)d_out;

    const int n = in_sizes[0] / FH;
    const int E = in_sizes[1] / 2;

    __half2* tmp1h; cudaGetSymbolAddress((void**)&tmp1h, g_tmp1h);
    float*   tmp2;  cudaGetSymbolAddress((void**)&tmp2,  g_tmp2);

    const int T  = 256;
    const int gE = (E + T - 1) / T;
    const int nb = (n + SCAN_T - 1) / SCAN_T;
    const int tiles = (n + 63) / 64;
    const int g1b = (tiles + G1_TILES - 1) / G1_TILES;

    k_hist   <<<gE + 1, T>>>(ei, E, n, W1, W2);   // +1 block = weight prep
    k_scan   <<<nb, SCAN_T>>>(n);
    k_scatter<<<gE, T>>>(E);

    k_gemm64_tc<<<g1b, 256>>>(x, tmp1h, n);
    k_layer2a  <<<(n + 127) / 128, 256>>>(tmp1h, (const float4*)b1, tmp2, n);
    k_agg2     <<<(n * 16 + T - 1) / T, T>>>(tmp2, b2, out, n);

    (void)n_in; (void)out_size;
}

// round 14
// speedup vs baseline: 1.7516x; 1.0445x over previous
#include <cuda_runtime.h>
#include <cuda_fp16.h>
#include <cstdint>

#define NN 100000
#define NE 800000
#define FH 64
#define FO 16
#define SCAN_T 1024
#define G1_TILES 2          // 64-row tiles per gemm64 block

// ---------------- scratch ----------------------------------------------------
__device__ int     g_cnt[NN + 128];   // [0,NN): in-degree; [NN,..): lookback slots
__device__ int     g_off[NN];         // CSR offsets; AFTER scatter = end pointers
__device__ float   g_dinv[NN];
__device__ int2    g_rc[NE];          // converted (src,dst) per edge
__device__ int2    g_sn[NE];          // CSR payload: (src, nrm bits)
__device__ __half2 g_tmp1h[(size_t)NN * 32];   // x @ W1, fp16
__device__ __half2 g_tmp2h[(size_t)NN * 8];    // gcn1(h) @ W2, fp16
__device__ __half  g_w1t[64 * 64];    // W1^T fp16: [n][k]
__device__ __half  g_w2t[16 * 64];    // W2^T fp16: [n][k]

// ---------------- helpers ----------------------------------------------------
__device__ __forceinline__ uint32_t smem_u32(const void* p) {
    return (uint32_t)__cvta_generic_to_shared(p);
}
__device__ __forceinline__ void cp_async16(uint32_t dst, const void* src, int sz) {
    asm volatile("cp.async.ca.shared.global [%0], [%1], 16, %2;"
                 :: "r"(dst), "l"(src), "r"(sz));
}
__device__ __forceinline__ int block_detect64(const void* edge, int n_nodes) {
    const long long* p = (const long long*)edge;
    long long v = p[threadIdx.x & 255];
    bool bad = (v < 0 || v >= (long long)n_nodes);
    return __syncthreads_or(bad ? 1 : 0) ? 0 : 1;
}

// ---------------- hist + edge convert + (last block) weight prep -------------
__global__ void k_hist(const void* edge, int E, int n_nodes,
                       const float* __restrict__ W1,
                       const float* __restrict__ W2) {
    if (blockIdx.x == gridDim.x - 1) {        // weight-prep block (concurrent)
        int tid = threadIdx.x;
        for (int i = tid; i < 64 * 64; i += 256) {
            int k = i >> 6, nn = i & 63;      // W1[k][n] -> w1t[n][k]
            g_w1t[nn * 64 + k] = __float2half_rn(W1[i]);
        }
        for (int i = tid; i < 64 * 16; i += 256) {
            int k = i >> 4, nn = i & 15;      // W2[k][n] -> w2t[n][k]
            g_w2t[nn * 64 + k] = __float2half_rn(W2[i]);
        }
        return;
    }
    int is64 = block_detect64(edge, n_nodes);
    int e = blockIdx.x * blockDim.x + threadIdx.x;
    if (e >= E) return;
    int r, c;
    if (is64) {
        const long long* p = (const long long*)edge;
        r = (int)p[e]; c = (int)p[e + E];
    } else {
        const int* p = (const int*)edge;
        r = p[e]; c = p[e + E];
    }
    g_rc[e] = make_int2(r, c);
    atomicAdd(&g_cnt[c], 1);
}

// ---------------- fused scan (deadlock-free lookback) + dinv -----------------
__global__ void k_scan(int n) {
    __shared__ int s[SCAN_T];
    __shared__ int s_pref;
    int b = blockIdx.x, t = threadIdx.x;
    int i = b * SCAN_T + t;
    int val = 0;
    if (i < n) {
        val = g_cnt[i];
        g_dinv[i] = rsqrtf((float)val + 1.0f);   // +1 self loop
    }
    s[t] = val;
    __syncthreads();
    for (int d = 1; d < SCAN_T; d <<= 1) {
        int add = (t >= d) ? s[t - d] : 0;
        __syncthreads();
        s[t] += add;
        __syncthreads();
    }
    if (t == SCAN_T - 1) atomicExch(&g_cnt[NN + b], s[t] + 1);   // publish first
    if (t == 0) s_pref = 0;
    __syncthreads();
    if (t < b) {
        int v;
        do { v = atomicAdd(&g_cnt[NN + t], 0); } while (v == 0);
        atomicAdd(&s_pref, v - 1);
    }
    __syncthreads();
    if (i < n) g_off[i] = s[t] - val + s_pref;
}

// ---------------- counting-sort scatter + lookback-slot cleanup --------------
__global__ void k_scatter(int E) {
    if (blockIdx.x == 0 && threadIdx.x < 128)
        g_cnt[NN + threadIdx.x] = 0;          // reset lookback slots for next call
    int e = blockIdx.x * blockDim.x + threadIdx.x;
    if (e >= E) return;
    int2 rc = g_rc[e];
    float nr = g_dinv[rc.x] * g_dinv[rc.y];
    int pos = atomicAdd(&g_off[rc.y], 1);
    g_sn[pos] = make_int2(rc.x, __float_as_int(nr));
}

// ---------------- GEMM1 (TC, pipelined): tmp1h = fp16(x @ W1) ----------------
__global__ void k_gemm64_tc(const float* __restrict__ A,
                            __half2* __restrict__ outh, int n) {
    __shared__ float  Xf[2][64][72];   // fp32 X tiles (reused for fp16 C staging)
    __shared__ __half Wts[64][72];     // W1^T [n][k]

    int tid  = threadIdx.x;
    int lane = tid & 31;
    int warp = tid >> 5;
    int q  = warp >> 2;                // col-half
    int w2 = warp & 3;                 // row group
    int g = lane >> 2, t = lane & 3;
    int row0 = w2 * 16;

    for (int idx = tid; idx < 512; idx += 256) {
        uint4 v = *(const uint4*)&g_w1t[idx * 8];
        *(uint4*)&Wts[idx >> 3][(idx & 7) * 8] = v;
    }

    int tile0 = blockIdx.x * G1_TILES;
    {
        int rb = tile0 * 64;
#pragma unroll
        for (int j = 0; j < 4; j++) {
            int idx = tid + j * 256;
            int r = idx >> 4, k4 = (idx & 15) << 2;
            int gr = rb + r;
            cp_async16(smem_u32(&Xf[0][r][k4]), A + (size_t)gr * 64 + k4,
                       (gr < n) ? 16 : 0);
        }
        asm volatile("cp.async.commit_group;");
    }

    for (int tt = 0; tt < G1_TILES; tt++) {
        int buf = tt & 1;
        int rb  = (tile0 + tt) * 64;

        if (tt + 1 < G1_TILES) {
            int rb2 = rb + 64;
#pragma unroll
            for (int j = 0; j < 4; j++) {
                int idx = tid + j * 256;
                int r = idx >> 4, k4 = (idx & 15) << 2;
                int gr = rb2 + r;
                cp_async16(smem_u32(&Xf[buf ^ 1][r][k4]), A + (size_t)gr * 64 + k4,
                           (gr < n) ? 16 : 0);
            }
            asm volatile("cp.async.commit_group;");
            asm volatile("cp.async.wait_group 1;");
        } else {
            asm volatile("cp.async.wait_group 0;");
        }
        __syncthreads();

        float acc[4][4];
#pragma unroll
        for (int j = 0; j < 4; j++)
#pragma unroll
            for (int m = 0; m < 4; m++) acc[j][m] = 0.f;

#pragma unroll
        for (int k0 = 0; k0 < 64; k0 += 16) {
            float2 f0 = *(const float2*)&Xf[buf][row0 + g    ][k0 + 2 * t];
            float2 f1 = *(const float2*)&Xf[buf][row0 + g + 8][k0 + 2 * t];
            float2 f2 = *(const float2*)&Xf[buf][row0 + g    ][k0 + 2 * t + 8];
            float2 f3 = *(const float2*)&Xf[buf][row0 + g + 8][k0 + 2 * t + 8];
            __half2 h0 = __floats2half2_rn(f0.x, f0.y);
            __half2 h1 = __floats2half2_rn(f1.x, f1.y);
            __half2 h2 = __floats2half2_rn(f2.x, f2.y);
            __half2 h3 = __floats2half2_rn(f3.x, f3.y);
            unsigned ra0 = *(unsigned*)&h0, ra1 = *(unsigned*)&h1;
            unsigned ra2 = *(unsigned*)&h2, ra3 = *(unsigned*)&h3;
#pragma unroll
            for (int j = 0; j < 4; j++) {
                int nt = q * 4 + j;
                unsigned rb0 = *(const unsigned*)&Wts[nt * 8 + g][k0 + 2 * t];
                unsigned rb1 = *(const unsigned*)&Wts[nt * 8 + g][k0 + 2 * t + 8];
                asm volatile(
                    "mma.sync.aligned.m16n8k16.row.col.f32.f16.f16.f32 "
                    "{%0,%1,%2,%3}, {%4,%5,%6,%7}, {%8,%9}, {%0,%1,%2,%3};"
                    : "+f"(acc[j][0]), "+f"(acc[j][1]),
                      "+f"(acc[j][2]), "+f"(acc[j][3])
                    : "r"(ra0), "r"(ra1), "r"(ra2), "r"(ra3),
                      "r"(rb0), "r"(rb1));
            }
        }
        __syncthreads();

#pragma unroll
        for (int j = 0; j < 4; j++) {
            int nt = q * 4 + j;
            __half2 c0 = __floats2half2_rn(acc[j][0], acc[j][1]);
            __half2 c1 = __floats2half2_rn(acc[j][2], acc[j][3]);
            *(__half2*)&Xf[buf][row0 + g    ][nt * 4 + t] = c0;
            *(__half2*)&Xf[buf][row0 + g + 8][nt * 4 + t] = c1;
        }
        __syncthreads();

        for (int idx = tid; idx < 512; idx += 256) {
            int r = idx >> 3, c = idx & 7;
            int gr = rb + r;
            if (gr < n) {
                uint4 v = *(const uint4*)&Xf[buf][r][c * 4];
                *(uint4*)&outh[(size_t)gr * 32 + c * 4] = v;
            }
        }
        __syncthreads();
    }
}

// ---------------- fused layer-2a: agg1 (into smem) + gemm16 -> fp16 ----------
__global__ void k_layer2a(const __half2* __restrict__ tmp,
                          const float4* __restrict__ b1,
                          __half2* __restrict__ outh, int n) {
    __shared__ __half Hs[128][72];
    __shared__ __half Wts[16][72];

    int tid  = threadIdx.x;
    int base = blockIdx.x * 128;
    int lane = tid & 31;
    int warp = tid >> 5;
    int g = lane >> 2, t = lane & 3;
    int l = tid & 7;                     // lane-in-node: half2 cols [4l, 4l+4)

    if (tid < 128) {
        uint4 v = *(const uint4*)&g_w2t[tid * 8];
        *(uint4*)&Wts[tid >> 3][(tid & 7) * 8] = v;
    }

    // Phase 1: aggregate 128 nodes, 32 nodes per batch (8 threads per node)
#pragma unroll
    for (int batch = 0; batch < 4; batch++) {
        int node = base + batch * 32 + (tid >> 3);
        float a0 = 0.f, a1 = 0.f, a2 = 0.f, a3 = 0.f,
              a4 = 0.f, a5 = 0.f, a6 = 0.f, a7 = 0.f;
        if (node < n) {
            float di = g_dinv[node];
            float ws = di * di;
            uint4 raw = *(const uint4*)&tmp[(size_t)node * 32 + 4 * l];
            float2 p;
            p = __half22float2(*(__half2*)&raw.x); a0 = p.x * ws; a1 = p.y * ws;
            p = __half22float2(*(__half2*)&raw.y); a2 = p.x * ws; a3 = p.y * ws;
            p = __half22float2(*(__half2*)&raw.z); a4 = p.x * ws; a5 = p.y * ws;
            p = __half22float2(*(__half2*)&raw.w); a6 = p.x * ws; a7 = p.y * ws;

            int e1 = g_off[node];
            int e  = e1 - g_cnt[node];
            for (; e + 2 <= e1; e += 2) {
                int2 q0 = g_sn[e];
                int2 q1 = g_sn[e + 1];
                uint4 r0 = *(const uint4*)&tmp[(size_t)q0.x * 32 + 4 * l];
                uint4 r1 = *(const uint4*)&tmp[(size_t)q1.x * 32 + 4 * l];
                float w0 = __int_as_float(q0.y), w1 = __int_as_float(q1.y);
                p = __half22float2(*(__half2*)&r0.x); a0 += p.x * w0; a1 += p.y * w0;
                p = __half22float2(*(__half2*)&r0.y); a2 += p.x * w0; a3 += p.y * w0;
                p = __half22float2(*(__half2*)&r0.z); a4 += p.x * w0; a5 += p.y * w0;
                p = __half22float2(*(__half2*)&r0.w); a6 += p.x * w0; a7 += p.y * w0;
                p = __half22float2(*(__half2*)&r1.x); a0 += p.x * w1; a1 += p.y * w1;
                p = __half22float2(*(__half2*)&r1.y); a2 += p.x * w1; a3 += p.y * w1;
                p = __half22float2(*(__half2*)&r1.z); a4 += p.x * w1; a5 += p.y * w1;
                p = __half22float2(*(__half2*)&r1.w); a6 += p.x * w1; a7 += p.y * w1;
            }
            if (e < e1) {
                int2 q0 = g_sn[e];
                uint4 r0 = *(const uint4*)&tmp[(size_t)q0.x * 32 + 4 * l];
                float w0 = __int_as_float(q0.y);
                p = __half22float2(*(__half2*)&r0.x); a0 += p.x * w0; a1 += p.y * w0;
                p = __half22float2(*(__half2*)&r0.y); a2 += p.x * w0; a3 += p.y * w0;
                p = __half22float2(*(__half2*)&r0.z); a4 += p.x * w0; a5 += p.y * w0;
                p = __half22float2(*(__half2*)&r0.w); a6 += p.x * w0; a7 += p.y * w0;
            }
            float4 bb0 = b1[2 * l];
            float4 bb1 = b1[2 * l + 1];
            a0 = fmaxf(a0 + bb0.x, 0.f); a1 = fmaxf(a1 + bb0.y, 0.f);
            a2 = fmaxf(a2 + bb0.z, 0.f); a3 = fmaxf(a3 + bb0.w, 0.f);
            a4 = fmaxf(a4 + bb1.x, 0.f); a5 = fmaxf(a5 + bb1.y, 0.f);
            a6 = fmaxf(a6 + bb1.z, 0.f); a7 = fmaxf(a7 + bb1.w, 0.f);
        }
        __half2 o0 = __floats2half2_rn(a0, a1);
        __half2 o1 = __floats2half2_rn(a2, a3);
        __half2 o2 = __floats2half2_rn(a4, a5);
        __half2 o3 = __floats2half2_rn(a6, a7);
        uint4 ov;
        ov.x = *(unsigned*)&o0; ov.y = *(unsigned*)&o1;
        ov.z = *(unsigned*)&o2; ov.w = *(unsigned*)&o3;
        *(uint4*)&Hs[batch * 32 + (tid >> 3)][l * 8] = ov;
    }
    __syncthreads();

    // Phase 2: MMA 128x16 = Hs @ W2t; emit fp16
    int row0 = warp * 16;
    float acc[2][4];
#pragma unroll
    for (int nt = 0; nt < 2; nt++)
#pragma unroll
        for (int j = 0; j < 4; j++) acc[nt][j] = 0.f;

#pragma unroll
    for (int k0 = 0; k0 < 64; k0 += 16) {
        unsigned ra0 = *(const unsigned*)&Hs[row0 + g    ][k0 + 2 * t];
        unsigned ra1 = *(const unsigned*)&Hs[row0 + g + 8][k0 + 2 * t];
        unsigned ra2 = *(const unsigned*)&Hs[row0 + g    ][k0 + 2 * t + 8];
        unsigned ra3 = *(const unsigned*)&Hs[row0 + g + 8][k0 + 2 * t + 8];
#pragma unroll
        for (int nt = 0; nt < 2; nt++) {
            unsigned rb0 = *(const unsigned*)&Wts[nt * 8 + g][k0 + 2 * t];
            unsigned rb1 = *(const unsigned*)&Wts[nt * 8 + g][k0 + 2 * t + 8];
            asm volatile(
                "mma.sync.aligned.m16n8k16.row.col.f32.f16.f16.f32 "
                "{%0,%1,%2,%3}, {%4,%5,%6,%7}, {%8,%9}, {%0,%1,%2,%3};"
                : "+f"(acc[nt][0]), "+f"(acc[nt][1]),
                  "+f"(acc[nt][2]), "+f"(acc[nt][3])
                : "r"(ra0), "r"(ra1), "r"(ra2), "r"(ra3),
                  "r"(rb0), "r"(rb1));
        }
    }

#pragma unroll
    for (int nt = 0; nt < 2; nt++) {
        int c0 = nt * 8 + 2 * t;             // even column
        int gr0 = base + row0 + g;
        int gr1 = gr0 + 8;
        if (gr0 < n)
            outh[(size_t)gr0 * 8 + (c0 >> 1)] = __floats2half2_rn(acc[nt][0], acc[nt][1]);
        if (gr1 < n)
            outh[(size_t)gr1 * 8 + (c0 >> 1)] = __floats2half2_rn(acc[nt][2], acc[nt][3]);
    }
}

// ---------------- aggregation, layer 2 (F=16, fp16 src) + cnt self-clean -----
// 8 threads per node; lane owns half2 cols {2l, 2l+1}.
__global__ void k_agg2h(const __half2* __restrict__ tmp,
                        const float2* __restrict__ b2,
                        float2* __restrict__ out, int n) {
    int i = (blockIdx.x * blockDim.x + threadIdx.x) >> 3;
    int l = threadIdx.x & 7;
    if (i >= n) return;
    float di = g_dinv[i];
    float ws = di * di;
    float2 v = __half22float2(tmp[(size_t)i * 8 + l]);
    float a0 = v.x * ws, a1 = v.y * ws;

    int e1 = g_off[i];
    int cnt = g_cnt[i];
    int e  = e1 - cnt;
    for (; e + 4 <= e1; e += 4) {
        int2 q0 = g_sn[e];
        int2 q1 = g_sn[e + 1];
        int2 q2 = g_sn[e + 2];
        int2 q3 = g_sn[e + 3];
        float2 t0 = __half22float2(tmp[(size_t)q0.x * 8 + l]);
        float2 t1 = __half22float2(tmp[(size_t)q1.x * 8 + l]);
        float2 t2 = __half22float2(tmp[(size_t)q2.x * 8 + l]);
        float2 t3 = __half22float2(tmp[(size_t)q3.x * 8 + l]);
        float w0 = __int_as_float(q0.y), w1 = __int_as_float(q1.y);
        float w2 = __int_as_float(q2.y), w3 = __int_as_float(q3.y);
        a0 += t0.x * w0; a1 += t0.y * w0;
        a0 += t1.x * w1; a1 += t1.y * w1;
        a0 += t2.x * w2; a1 += t2.y * w2;
        a0 += t3.x * w3; a1 += t3.y * w3;
    }
    for (; e < e1; e++) {
        int2 q = g_sn[e];
        float2 tv = __half22float2(tmp[(size_t)q.x * 8 + l]);
        float w = __int_as_float(q.y);
        a0 += tv.x * w; a1 += tv.y * w;
    }
    float2 bb = b2[l];
    out[(size_t)i * 8 + l] = make_float2(a0 + bb.x, a1 + bb.y);
    if (l == 0) g_cnt[i] = 0;            // restore pre-call invariant
}

// ---------------- launcher ---------------------------------------------------
extern "C" void kernel_launch(void* const* d_in, const int* in_sizes, int n_in,
                              void* d_out, int out_size) {
    const float* x  = (const float*)d_in[0];
    const void*  ei = d_in[1];
    const float* W1 = (const float*)d_in[2];
    const float* b1 = (const float*)d_in[3];
    const float* W2 = (const float*)d_in[4];
    const float* b2 = (const float*)d_in[5];
    float* out = (float*)d_out;

    const int n = in_sizes[0] / FH;
    const int E = in_sizes[1] / 2;

    __half2* tmp1h; cudaGetSymbolAddress((void**)&tmp1h, g_tmp1h);
    __half2* tmp2h; cudaGetSymbolAddress((void**)&tmp2h, g_tmp2h);

    const int T  = 256;
    const int gE = (E + T - 1) / T;
    const int nb = (n + SCAN_T - 1) / SCAN_T;
    const int tiles = (n + 63) / 64;
    const int g1b = (tiles + G1_TILES - 1) / G1_TILES;

    k_hist   <<<gE + 1, T>>>(ei, E, n, W1, W2);   // +1 block = weight prep
    k_scan   <<<nb, SCAN_T>>>(n);
    k_scatter<<<gE, T>>>(E);

    k_gemm64_tc<<<g1b, 256>>>(x, tmp1h, n);
    k_layer2a  <<<(n + 127) / 128, 256>>>(tmp1h, (const float4*)b1, tmp2h, n);
    k_agg2h    <<<(n * 8 + T - 1) / T, T>>>(tmp2h, (const float2*)b2,
                                            (float2*)out, n);

    (void)n_in; (void)out_size;
}

// round 16
// speedup vs baseline: 1.7675x; 1.0091x over previous
#include <cuda_runtime.h>
#include <cuda_fp16.h>
#include <cstdint>

#define NN 100000
#define NE 800000
#define FH 64
#define FO 16
#define SCAN_T 1024
#define G1_TILES 2          // 64-row tiles per gemm64 block

// ---------------- scratch ----------------------------------------------------
__device__ int     g_cnt[NN + 128];   // [0,NN): in-degree; [NN,..): lookback slots
__device__ int     g_off[NN];         // CSR offsets; AFTER scatter = end pointers
__device__ float   g_dinv[NN];
__device__ int2    g_rc[NE];          // converted (src,dst) per edge
__device__ int2    g_sn[NE];          // CSR payload: (src, nrm bits)
__device__ __half2 g_tmp1h[(size_t)NN * 32];   // x @ W1, fp16
__device__ __half2 g_tmp2h[(size_t)NN * 8];    // gcn1(h) @ W2, fp16
__device__ __half  g_w1t[64 * 64];    // W1^T fp16: [n][k]
__device__ __half  g_w2t[16 * 64];    // W2^T fp16: [n][k]

// ---------------- helpers ----------------------------------------------------
__device__ __forceinline__ uint32_t smem_u32(const void* p) {
    return (uint32_t)__cvta_generic_to_shared(p);
}
__device__ __forceinline__ void cp_async16(uint32_t dst, const void* src, int sz) {
    asm volatile("cp.async.ca.shared.global [%0], [%1], 16, %2;"
                 :: "r"(dst), "l"(src), "r"(sz));
}
__device__ __forceinline__ int block_detect64(const void* edge, int n_nodes) {
    const long long* p = (const long long*)edge;
    long long v = p[threadIdx.x & 255];
    bool bad = (v < 0 || v >= (long long)n_nodes);
    return __syncthreads_or(bad ? 1 : 0) ? 0 : 1;
}

// ---------------- hist + edge convert + (last block) weight prep -------------
__global__ void k_hist(const void* edge, int E, int n_nodes,
                       const float* __restrict__ W1,
                       const float* __restrict__ W2) {
    if (blockIdx.x == gridDim.x - 1) {        // weight-prep block (concurrent)
        int tid = threadIdx.x;
        for (int i = tid; i < 64 * 64; i += 256) {
            int k = i >> 6, nn = i & 63;      // W1[k][n] -> w1t[n][k]
            g_w1t[nn * 64 + k] = __float2half_rn(W1[i]);
        }
        for (int i = tid; i < 64 * 16; i += 256) {
            int k = i >> 4, nn = i & 15;      // W2[k][n] -> w2t[n][k]
            g_w2t[nn * 64 + k] = __float2half_rn(W2[i]);
        }
        return;
    }
    int is64 = block_detect64(edge, n_nodes);
    int e = blockIdx.x * blockDim.x + threadIdx.x;
    if (e >= E) return;
    int r, c;
    if (is64) {
        const long long* p = (const long long*)edge;
        r = (int)p[e]; c = (int)p[e + E];
    } else {
        const int* p = (const int*)edge;
        r = p[e]; c = p[e + E];
    }
    g_rc[e] = make_int2(r, c);
    atomicAdd(&g_cnt[c], 1);
}

// ---------------- fused scan (deadlock-free lookback) + dinv -----------------
__global__ void k_scan(int n) {
    __shared__ int s[SCAN_T];
    __shared__ int s_pref;
    int b = blockIdx.x, t = threadIdx.x;
    int i = b * SCAN_T + t;
    int val = 0;
    if (i < n) {
        val = g_cnt[i];
        g_dinv[i] = rsqrtf((float)val + 1.0f);   // +1 self loop
    }
    s[t] = val;
    __syncthreads();
    for (int d = 1; d < SCAN_T; d <<= 1) {
        int add = (t >= d) ? s[t - d] : 0;
        __syncthreads();
        s[t] += add;
        __syncthreads();
    }
    if (t == SCAN_T - 1) atomicExch(&g_cnt[NN + b], s[t] + 1);   // publish first
    if (t == 0) s_pref = 0;
    __syncthreads();
    if (t < b) {
        int v;
        do { v = atomicAdd(&g_cnt[NN + t], 0); } while (v == 0);
        atomicAdd(&s_pref, v - 1);
    }
    __syncthreads();
    if (i < n) g_off[i] = s[t] - val + s_pref;
}

// ---------------- merged: gemm64 (blocks [0,g1b)) + scatter (rest) -----------
// Independent work units fused into one launch so scatter's atomic-latency
// phase overlaps gemm64's load/MMA phases on the same SMs.
__global__ void k_scat_gemm(int E,
                            const float* __restrict__ A,
                            __half2* __restrict__ outh, int n, int g1b) {
    __shared__ float  Xf[2][64][72];   // gemm: fp32 X tiles (reused for C staging)
    __shared__ __half Wts[64][72];     // gemm: W1^T [n][k]

    int tid = threadIdx.x;

    if (blockIdx.x >= g1b) {
        // ---------------- scatter branch ----------------
        int sb = blockIdx.x - g1b;
        if (sb == 0 && tid < 128)
            g_cnt[NN + tid] = 0;              // reset lookback slots for next call
        int e = sb * blockDim.x + tid;
        if (e >= E) return;
        int2 rc = g_rc[e];
        float nr = g_dinv[rc.x] * g_dinv[rc.y];
        int pos = atomicAdd(&g_off[rc.y], 1);
        g_sn[pos] = make_int2(rc.x, __float_as_int(nr));
        return;
    }

    // ---------------- gemm64 branch ----------------
    int lane = tid & 31;
    int warp = tid >> 5;
    int q  = warp >> 2;                // col-half
    int w2 = warp & 3;                 // row group
    int g = lane >> 2, t = lane & 3;
    int row0 = w2 * 16;

    for (int idx = tid; idx < 512; idx += 256) {
        uint4 v = *(const uint4*)&g_w1t[idx * 8];
        *(uint4*)&Wts[idx >> 3][(idx & 7) * 8] = v;
    }

    int tile0 = blockIdx.x * G1_TILES;
    {
        int rb = tile0 * 64;
#pragma unroll
        for (int j = 0; j < 4; j++) {
            int idx = tid + j * 256;
            int r = idx >> 4, k4 = (idx & 15) << 2;
            int gr = rb + r;
            cp_async16(smem_u32(&Xf[0][r][k4]), A + (size_t)gr * 64 + k4,
                       (gr < n) ? 16 : 0);
        }
        asm volatile("cp.async.commit_group;");
    }

    for (int tt = 0; tt < G1_TILES; tt++) {
        int buf = tt & 1;
        int rb  = (tile0 + tt) * 64;

        if (tt + 1 < G1_TILES) {
            int rb2 = rb + 64;
#pragma unroll
            for (int j = 0; j < 4; j++) {
                int idx = tid + j * 256;
                int r = idx >> 4, k4 = (idx & 15) << 2;
                int gr = rb2 + r;
                cp_async16(smem_u32(&Xf[buf ^ 1][r][k4]), A + (size_t)gr * 64 + k4,
                           (gr < n) ? 16 : 0);
            }
            asm volatile("cp.async.commit_group;");
            asm volatile("cp.async.wait_group 1;");
        } else {
            asm volatile("cp.async.wait_group 0;");
        }
        __syncthreads();

        float acc[4][4];
#pragma unroll
        for (int j = 0; j < 4; j++)
#pragma unroll
            for (int m = 0; m < 4; m++) acc[j][m] = 0.f;

#pragma unroll
        for (int k0 = 0; k0 < 64; k0 += 16) {
            float2 f0 = *(const float2*)&Xf[buf][row0 + g    ][k0 + 2 * t];
            float2 f1 = *(const float2*)&Xf[buf][row0 + g + 8][k0 + 2 * t];
            float2 f2 = *(const float2*)&Xf[buf][row0 + g    ][k0 + 2 * t + 8];
            float2 f3 = *(const float2*)&Xf[buf][row0 + g + 8][k0 + 2 * t + 8];
            __half2 h0 = __floats2half2_rn(f0.x, f0.y);
            __half2 h1 = __floats2half2_rn(f1.x, f1.y);
            __half2 h2 = __floats2half2_rn(f2.x, f2.y);
            __half2 h3 = __floats2half2_rn(f3.x, f3.y);
            unsigned ra0 = *(unsigned*)&h0, ra1 = *(unsigned*)&h1;
            unsigned ra2 = *(unsigned*)&h2, ra3 = *(unsigned*)&h3;
#pragma unroll
            for (int j = 0; j < 4; j++) {
                int nt = q * 4 + j;
                unsigned rb0 = *(const unsigned*)&Wts[nt * 8 + g][k0 + 2 * t];
                unsigned rb1 = *(const unsigned*)&Wts[nt * 8 + g][k0 + 2 * t + 8];
                asm volatile(
                    "mma.sync.aligned.m16n8k16.row.col.f32.f16.f16.f32 "
                    "{%0,%1,%2,%3}, {%4,%5,%6,%7}, {%8,%9}, {%0,%1,%2,%3};"
                    : "+f"(acc[j][0]), "+f"(acc[j][1]),
                      "+f"(acc[j][2]), "+f"(acc[j][3])
                    : "r"(ra0), "r"(ra1), "r"(ra2), "r"(ra3),
                      "r"(rb0), "r"(rb1));
            }
        }
        __syncthreads();

#pragma unroll
        for (int j = 0; j < 4; j++) {
            int nt = q * 4 + j;
            __half2 c0 = __floats2half2_rn(acc[j][0], acc[j][1]);
            __half2 c1 = __floats2half2_rn(acc[j][2], acc[j][3]);
            *(__half2*)&Xf[buf][row0 + g    ][nt * 4 + t] = c0;
            *(__half2*)&Xf[buf][row0 + g + 8][nt * 4 + t] = c1;
        }
        __syncthreads();

        for (int idx = tid; idx < 512; idx += 256) {
            int r = idx >> 3, c = idx & 7;
            int gr = rb + r;
            if (gr < n) {
                uint4 v = *(const uint4*)&Xf[buf][r][c * 4];
                *(uint4*)&outh[(size_t)gr * 32 + c * 4] = v;
            }
        }
        __syncthreads();
    }
}

// ---------------- fused layer-2a: agg1 (into smem) + gemm16 -> fp16 ----------
__global__ void k_layer2a(const __half2* __restrict__ tmp,
                          const float4* __restrict__ b1,
                          __half2* __restrict__ outh, int n) {
    __shared__ __half Hs[128][72];
    __shared__ __half Wts[16][72];

    int tid  = threadIdx.x;
    int base = blockIdx.x * 128;
    int lane = tid & 31;
    int warp = tid >> 5;
    int g = lane >> 2, t = lane & 3;
    int l = tid & 7;                     // lane-in-node: half2 cols [4l, 4l+4)

    if (tid < 128) {
        uint4 v = *(const uint4*)&g_w2t[tid * 8];
        *(uint4*)&Wts[tid >> 3][(tid & 7) * 8] = v;
    }

    // Phase 1: aggregate 128 nodes, 32 nodes per batch (8 threads per node)
#pragma unroll
    for (int batch = 0; batch < 4; batch++) {
        int node = base + batch * 32 + (tid >> 3);
        float a0 = 0.f, a1 = 0.f, a2 = 0.f, a3 = 0.f,
              a4 = 0.f, a5 = 0.f, a6 = 0.f, a7 = 0.f;
        if (node < n) {
            float di = g_dinv[node];
            float ws = di * di;
            uint4 raw = *(const uint4*)&tmp[(size_t)node * 32 + 4 * l];
            float2 p;
            p = __half22float2(*(__half2*)&raw.x); a0 = p.x * ws; a1 = p.y * ws;
            p = __half22float2(*(__half2*)&raw.y); a2 = p.x * ws; a3 = p.y * ws;
            p = __half22float2(*(__half2*)&raw.z); a4 = p.x * ws; a5 = p.y * ws;
            p = __half22float2(*(__half2*)&raw.w); a6 = p.x * ws; a7 = p.y * ws;

            int e1 = g_off[node];
            int e  = e1 - g_cnt[node];
            for (; e + 2 <= e1; e += 2) {
                int2 q0 = g_sn[e];
                int2 q1 = g_sn[e + 1];
                uint4 r0 = *(const uint4*)&tmp[(size_t)q0.x * 32 + 4 * l];
                uint4 r1 = *(const uint4*)&tmp[(size_t)q1.x * 32 + 4 * l];
                float w0 = __int_as_float(q0.y), w1 = __int_as_float(q1.y);
                p = __half22float2(*(__half2*)&r0.x); a0 += p.x * w0; a1 += p.y * w0;
                p = __half22float2(*(__half2*)&r0.y); a2 += p.x * w0; a3 += p.y * w0;
                p = __half22float2(*(__half2*)&r0.z); a4 += p.x * w0; a5 += p.y * w0;
                p = __half22float2(*(__half2*)&r0.w); a6 += p.x * w0; a7 += p.y * w0;
                p = __half22float2(*(__half2*)&r1.x); a0 += p.x * w1; a1 += p.y * w1;
                p = __half22float2(*(__half2*)&r1.y); a2 += p.x * w1; a3 += p.y * w1;
                p = __half22float2(*(__half2*)&r1.z); a4 += p.x * w1; a5 += p.y * w1;
                p = __half22float2(*(__half2*)&r1.w); a6 += p.x * w1; a7 += p.y * w1;
            }
            if (e < e1) {
                int2 q0 = g_sn[e];
                uint4 r0 = *(const uint4*)&tmp[(size_t)q0.x * 32 + 4 * l];
                float w0 = __int_as_float(q0.y);
                p = __half22float2(*(__half2*)&r0.x); a0 += p.x * w0; a1 += p.y * w0;
                p = __half22float2(*(__half2*)&r0.y); a2 += p.x * w0; a3 += p.y * w0;
                p = __half22float2(*(__half2*)&r0.z); a4 += p.x * w0; a5 += p.y * w0;
                p = __half22float2(*(__half2*)&r0.w); a6 += p.x * w0; a7 += p.y * w0;
            }
            float4 bb0 = b1[2 * l];
            float4 bb1 = b1[2 * l + 1];
            a0 = fmaxf(a0 + bb0.x, 0.f); a1 = fmaxf(a1 + bb0.y, 0.f);
            a2 = fmaxf(a2 + bb0.z, 0.f); a3 = fmaxf(a3 + bb0.w, 0.f);
            a4 = fmaxf(a4 + bb1.x, 0.f); a5 = fmaxf(a5 + bb1.y, 0.f);
            a6 = fmaxf(a6 + bb1.z, 0.f); a7 = fmaxf(a7 + bb1.w, 0.f);
        }
        __half2 o0 = __floats2half2_rn(a0, a1);
        __half2 o1 = __floats2half2_rn(a2, a3);
        __half2 o2 = __floats2half2_rn(a4, a5);
        __half2 o3 = __floats2half2_rn(a6, a7);
        uint4 ov;
        ov.x = *(unsigned*)&o0; ov.y = *(unsigned*)&o1;
        ov.z = *(unsigned*)&o2; ov.w = *(unsigned*)&o3;
        *(uint4*)&Hs[batch * 32 + (tid >> 3)][l * 8] = ov;
    }
    __syncthreads();

    // Phase 2: MMA 128x16 = Hs @ W2t; emit fp16
    int row0 = warp * 16;
    float acc[2][4];
#pragma unroll
    for (int nt = 0; nt < 2; nt++)
#pragma unroll
        for (int j = 0; j < 4; j++) acc[nt][j] = 0.f;

#pragma unroll
    for (int k0 = 0; k0 < 64; k0 += 16) {
        unsigned ra0 = *(const unsigned*)&Hs[row0 + g    ][k0 + 2 * t];
        unsigned ra1 = *(const unsigned*)&Hs[row0 + g + 8][k0 + 2 * t];
        unsigned ra2 = *(const unsigned*)&Hs[row0 + g    ][k0 + 2 * t + 8];
        unsigned ra3 = *(const unsigned*)&Hs[row0 + g + 8][k0 + 2 * t + 8];
#pragma unroll
        for (int nt = 0; nt < 2; nt++) {
            unsigned rb0 = *(const unsigned*)&Wts[nt * 8 + g][k0 + 2 * t];
            unsigned rb1 = *(const unsigned*)&Wts[nt * 8 + g][k0 + 2 * t + 8];
            asm volatile(
                "mma.sync.aligned.m16n8k16.row.col.f32.f16.f16.f32 "
                "{%0,%1,%2,%3}, {%4,%5,%6,%7}, {%8,%9}, {%0,%1,%2,%3};"
                : "+f"(acc[nt][0]), "+f"(acc[nt][1]),
                  "+f"(acc[nt][2]), "+f"(acc[nt][3])
                : "r"(ra0), "r"(ra1), "r"(ra2), "r"(ra3),
                  "r"(rb0), "r"(rb1));
        }
    }

#pragma unroll
    for (int nt = 0; nt < 2; nt++) {
        int c0 = nt * 8 + 2 * t;             // even column
        int gr0 = base + row0 + g;
        int gr1 = gr0 + 8;
        if (gr0 < n)
            outh[(size_t)gr0 * 8 + (c0 >> 1)] = __floats2half2_rn(acc[nt][0], acc[nt][1]);
        if (gr1 < n)
            outh[(size_t)gr1 * 8 + (c0 >> 1)] = __floats2half2_rn(acc[nt][2], acc[nt][3]);
    }
}

// ---------------- aggregation, layer 2 (F=16, fp16 src) + cnt self-clean -----
__global__ void k_agg2h(const __half2* __restrict__ tmp,
                        const float2* __restrict__ b2,
                        float2* __restrict__ out, int n) {
    int i = (blockIdx.x * blockDim.x + threadIdx.x) >> 3;
    int l = threadIdx.x & 7;
    if (i >= n) return;
    float di = g_dinv[i];
    float ws = di * di;
    float2 v = __half22float2(tmp[(size_t)i * 8 + l]);
    float a0 = v.x * ws, a1 = v.y * ws;

    int e1 = g_off[i];
    int cnt = g_cnt[i];
    int e  = e1 - cnt;
    for (; e + 4 <= e1; e += 4) {
        int2 q0 = g_sn[e];
        int2 q1 = g_sn[e + 1];
        int2 q2 = g_sn[e + 2];
        int2 q3 = g_sn[e + 3];
        float2 t0 = __half22float2(tmp[(size_t)q0.x * 8 + l]);
        float2 t1 = __half22float2(tmp[(size_t)q1.x * 8 + l]);
        float2 t2 = __half22float2(tmp[(size_t)q2.x * 8 + l]);
        float2 t3 = __half22float2(tmp[(size_t)q3.x * 8 + l]);
        float w0 = __int_as_float(q0.y), w1 = __int_as_float(q1.y);
        float w2 = __int_as_float(q2.y), w3 = __int_as_float(q3.y);
        a0 += t0.x * w0; a1 += t0.y * w0;
        a0 += t1.x * w1; a1 += t1.y * w1;
        a0 += t2.x * w2; a1 += t2.y * w2;
        a0 += t3.x * w3; a1 += t3.y * w3;
    }
    for (; e < e1; e++) {
        int2 q = g_sn[e];
        float2 tv = __half22float2(tmp[(size_t)q.x * 8 + l]);
        float w = __int_as_float(q.y);
        a0 += tv.x * w; a1 += tv.y * w;
    }
    float2 bb = b2[l];
    out[(size_t)i * 8 + l] = make_float2(a0 + bb.x, a1 + bb.y);
    if (l == 0) g_cnt[i] = 0;            // restore pre-call invariant
}

// ---------------- launcher ---------------------------------------------------
extern "C" void kernel_launch(void* const* d_in, const int* in_sizes, int n_in,
                              void* d_out, int out_size) {
    const float* x  = (const float*)d_in[0];
    const void*  ei = d_in[1];
    const float* W1 = (const float*)d_in[2];
    const float* b1 = (const float*)d_in[3];
    const float* W2 = (const float*)d_in[4];
    const float* b2 = (const float*)d_in[5];
    float* out = (float*)d_out;

    const int n = in_sizes[0] / FH;
    const int E = in_sizes[1] / 2;

    __half2* tmp1h; cudaGetSymbolAddress((void**)&tmp1h, g_tmp1h);
    __half2* tmp2h; cudaGetSymbolAddress((void**)&tmp2h, g_tmp2h);

    const int T  = 256;
    const int gE = (E + T - 1) / T;
    const int nb = (n + SCAN_T - 1) / SCAN_T;
    const int tiles = (n + 63) / 64;
    const int g1b = (tiles + G1_TILES - 1) / G1_TILES;

    k_hist     <<<gE + 1, T>>>(ei, E, n, W1, W2);   // +1 block = weight prep
    k_scan     <<<nb, SCAN_T>>>(n);
    k_scat_gemm<<<g1b + gE, T>>>(E, x, tmp1h, n, g1b);   // scatter ∥ gemm64
    k_layer2a  <<<(n + 127) / 128, 256>>>(tmp1h, (const float4*)b1, tmp2h, n);
    k_agg2h    <<<(n * 8 + T - 1) / T, T>>>(tmp2h, (const float2*)b2,
                                            (float2*)out, n);

    (void)n_in; (void)out_size;
}